// round 10
// baseline (speedup 1.0000x reference)
#include <cuda_runtime.h>
#include <cuda_bf16.h>
#include <math.h>
#include <stdint.h>

// Problem dims
#define BB 64
#define NNODE 64
#define DD 128
#define NHH 2
#define LLAYERS 2
#define ROWS (BB*NNODE)          // 4096

// ============================================================================
// Helpers
// ============================================================================
__device__ __forceinline__ uint32_t smem_u32(const void* p) {
    uint32_t a;
    asm("{ .reg .u64 t; cvta.to.shared.u64 t, %1; cvt.u32.u64 %0, t; }"
        : "=r"(a) : "l"(p));
    return a;
}

__device__ __forceinline__ void ldmA(uint32_t* a, uint32_t addr) {
    asm volatile("ldmatrix.sync.aligned.m8n8.x4.shared.b16 {%0,%1,%2,%3}, [%4];"
        : "=r"(a[0]), "=r"(a[1]), "=r"(a[2]), "=r"(a[3]) : "r"(addr));
}
__device__ __forceinline__ void ldmBt(uint32_t* b, uint32_t addr) {
    asm volatile("ldmatrix.sync.aligned.m8n8.x2.trans.shared.b16 {%0,%1}, [%2];"
        : "=r"(b[0]), "=r"(b[1]) : "r"(addr));
}
__device__ __forceinline__ void mma16816(float* d, const uint32_t* a, const uint32_t* b) {
    asm volatile("mma.sync.aligned.m16n8k16.row.col.f32.bf16.bf16.f32 "
        "{%0,%1,%2,%3}, {%4,%5,%6,%7}, {%8,%9}, {%0,%1,%2,%3};"
        : "+f"(d[0]), "+f"(d[1]), "+f"(d[2]), "+f"(d[3])
        : "r"(a[0]), "r"(a[1]), "r"(a[2]), "r"(a[3]), "r"(b[0]), "r"(b[1]));
}
__device__ __forceinline__ void cp16(uint32_t saddr, const void* gptr) {
    asm volatile("cp.async.cg.shared.global [%0], [%1], 16;"
        :: "r"(saddr), "l"(gptr));
}
#define CP_COMMIT() asm volatile("cp.async.commit_group;" ::: "memory")
template <int N>
__device__ __forceinline__ void cp_wait() {
    asm volatile("cp.async.wait_group %0;" :: "n"(N) : "memory");
}

__device__ __forceinline__ void bf16split(float v, __nv_bfloat16* hi, __nv_bfloat16* lo) {
    __nv_bfloat16 h = __float2bfloat16(v);
    *hi = h;
    *lo = __float2bfloat16(v - __bfloat162float(h));
}

// ============================================================================
// Scratch (device globals; no allocation)
// ============================================================================
__device__ __nv_bfloat16 g_x0h [ROWS*256];
__device__ __nv_bfloat16 g_x0l [ROWS*256];
__device__ float         g_emb [ROWS*128];
__device__ __nv_bfloat16 g_hh  [ROWS*128];
__device__ __nv_bfloat16 g_hl  [ROWS*128];
__device__ float         g_qkv [ROWS*1024];
__device__ __nv_bfloat16 g_mhah[ROWS*512];
__device__ __nv_bfloat16 g_mhal[ROWS*512];
__device__ __nv_bfloat16 g_ffh [ROWS*512];
__device__ __nv_bfloat16 g_ffl [ROWS*512];
__device__ float         g_cvec[LLAYERS*128];
__device__ int           g_mask_mode;

// Weight images, natural [K][N] bf16, hi plane then lo plane
__device__ __nv_bfloat16 g_WnImg  [2*256*128];
__device__ __nv_bfloat16 g_WprojImg[LLAYERS][2*128*1024];
__device__ __nv_bfloat16 g_WbigImg [LLAYERS][2*512*128];
__device__ __nv_bfloat16 g_W1Img   [LLAYERS][2*128*512];
__device__ __nv_bfloat16 g_W2Img   [LLAYERS][2*512*128];

// ============================================================================
// mask dtype detection (parallel)
// ============================================================================
__global__ void detect_mask_kernel(const unsigned char* __restrict__ m)
{
    __shared__ int cnt[2];
    if (threadIdx.x < 2) cnt[threadIdx.x] = 0;
    __syncthreads();
    int u8 = 0, f32 = 0;
    for (int i = threadIdx.x; i < 4096; i += 256) {
        unsigned char v = m[i];
        if (v) {
            int r = i & 3;
            if (r == 1) u8++;
            else if (r == 3) f32++;
        }
    }
    if (u8)  atomicAdd(&cnt[0], u8);
    if (f32) atomicAdd(&cnt[1], f32);
    __syncthreads();
    if (threadIdx.x == 0)
        g_mask_mode = cnt[0] ? 0 : (cnt[1] ? 2 : 1);
}
__device__ __forceinline__ bool mask_at(const void* mp, size_t idx, int mode)
{
    if (mode == 0) return ((const unsigned char*)mp)[idx] != 0;
    if (mode == 1) return ((const int*)mp)[idx] != 0;
    return ((const float*)mp)[idx] != 0.0f;
}

// ============================================================================
// Fused prologue: ALL weight-image prep in one kernel (blockIdx dispatch)
// ============================================================================
#define PREP_BLOCKS (128 + 768 + 256 + 256 + 256 + 512 + 512 + 1)
__global__ void fused_prep(const float* __restrict__ Wn, const float* __restrict__ Wq,
                           const float* __restrict__ Wk, const float* __restrict__ Wv,
                           const float* __restrict__ We, const float* __restrict__ Wo,
                           const float* __restrict__ W1, const float* __restrict__ W2,
                           const float* __restrict__ be, const float* __restrict__ bo)
{
    int blk = blockIdx.x, tid = threadIdx.x;
    __nv_bfloat16 hi, lo;

    if (blk < 128) {
        int t = blk * 256 + tid;
        bf16split(Wn[t], &hi, &lo);
        g_WnImg[t] = hi; g_WnImg[32768 + t] = lo;
        return;
    }
    blk -= 128;
    if (blk < 768) {
        int idx = blk * 256 + tid;
        int l = idx / 98304, r = idx % 98304;
        int k = r / 768, n = r % 768;
        const float* W = (n < 256) ? Wq : (n < 512 ? Wk : Wv);
        float v = W[(size_t)l * 32768 + (size_t)k * 256 + (n & 255)];
        bf16split(v, &hi, &lo);
        g_WprojImg[l][(size_t)k * 1024 + n]          = hi;
        g_WprojImg[l][131072 + (size_t)k * 1024 + n] = lo;
        return;
    }
    blk -= 768;
    if (blk < 256) {
        int idx = blk * 256 + tid;
        int l = idx >> 15, r = idx & 32767;
        int h = r >> 14, r2 = r & 16383;
        int e = r2 >> 7, d = r2 & 127;
        const float* wq = Wq + (size_t)l * 32768 + (size_t)d * 256 + h * 128;
        const float* we = We + (size_t)l * 16384 + (size_t)e * 128;
        float acc = 0.0f;
        #pragma unroll 8
        for (int c = 0; c < 128; c++) acc += wq[c] * we[c];
        size_t o = (size_t)d * 1024 + 768 + h * 128 + e;
        bf16split(acc, &hi, &lo);
        g_WprojImg[l][o] = hi; g_WprojImg[l][131072 + o] = lo;
        return;
    }
    blk -= 256;
    if (blk < 256) {
        int idx = blk * 256 + tid;
        int l = idx >> 15, t2 = idx & 32767;
        bf16split(Wo[(size_t)l * 32768 + t2], &hi, &lo);
        g_WbigImg[l][t2] = hi; g_WbigImg[l][65536 + t2] = lo;
        return;
    }
    blk -= 256;
    if (blk < 256) {
        int idx = blk * 256 + tid;
        int l = idx >> 15, r = idx & 32767;
        int h = r >> 14, r2 = r & 16383;
        int f = r2 >> 7, n = r2 & 127;
        const float* we = We + (size_t)l * 16384 + (size_t)f * 128;
        const float* wo = Wo + (size_t)l * 32768 + (size_t)(h * 128) * 128 + n;
        float acc = 0.0f;
        #pragma unroll 8
        for (int e = 0; e < 128; e++) acc += we[e] * wo[(size_t)e * 128];
        size_t o = (size_t)(256 + h * 128 + f) * 128 + n;
        bf16split(acc, &hi, &lo);
        g_WbigImg[l][o] = hi; g_WbigImg[l][65536 + o] = lo;
        return;
    }
    blk -= 256;
    if (blk < 512) {
        int idx = blk * 256 + tid;
        int l = idx >> 16, t2 = idx & 65535;
        bf16split(W1[(size_t)l * 65536 + t2], &hi, &lo);
        g_W1Img[l][t2] = hi; g_W1Img[l][65536 + t2] = lo;
        return;
    }
    blk -= 512;
    if (blk < 512) {
        int idx = blk * 256 + tid;
        int l = idx >> 16, t2 = idx & 65535;
        bf16split(W2[(size_t)l * 65536 + t2], &hi, &lo);
        g_W2Img[l][t2] = hi; g_W2Img[l][65536 + t2] = lo;
        return;
    }
    blk -= 512;
    {
        int l = tid >> 7, d = tid & 127;
        float acc = bo[l * 128 + d];
        const float* wo = Wo + (size_t)l * 32768;
        const float* bel = be + l * 128;
        for (int r = 0; r < 256; r++) acc += bel[r & 127] * wo[(size_t)r * 128 + d];
        g_cvec[l * 128 + d] = acc;
    }
}

// ============================================================================
// concat(node_feat, stpe) -> bf16 pairs [4096,256]
// ============================================================================
__global__ void concat_kernel(const float* __restrict__ nf, const float* __restrict__ st)
{
    int t = blockIdx.x * blockDim.x + threadIdx.x;
    if (t < ROWS * 64) {
        int row = t >> 6, c4 = t & 63;
        float4 val = (c4 < 32) ? ((const float4*)nf)[row * 32 + c4]
                               : ((const float4*)st)[row * 32 + (c4 - 32)];
        size_t o = (size_t)row * 256 + c4 * 4;
        float vv[4] = {val.x, val.y, val.z, val.w};
        #pragma unroll
        for (int j = 0; j < 4; j++) {
            __nv_bfloat16 hi, lo; bf16split(vv[j], &hi, &lo);
            g_x0h[o + j] = hi; g_x0l[o + j] = lo;
        }
    }
}

// ============================================================================
// LayerNorm -> bf16 pairs
// ============================================================================
__global__ void ln_kernel(const float* __restrict__ x,
                          const float* __restrict__ g, const float* __restrict__ b,
                          float eps)
{
    int row  = blockIdx.x * 8 + (threadIdx.x >> 5);
    int lane = threadIdx.x & 31;
    const float* xr = x + (size_t)row * 128;
    float v0 = xr[lane], v1 = xr[lane + 32], v2 = xr[lane + 64], v3 = xr[lane + 96];
    float s = v0 + v1 + v2 + v3;
    #pragma unroll
    for (int o = 16; o; o >>= 1) s += __shfl_xor_sync(0xffffffffu, s, o);
    float mu = s * (1.0f / 128.0f);
    float d0 = v0 - mu, d1 = v1 - mu, d2 = v2 - mu, d3 = v3 - mu;
    float q = d0*d0 + d1*d1 + d2*d2 + d3*d3;
    #pragma unroll
    for (int o = 16; o; o >>= 1) q += __shfl_xor_sync(0xffffffffu, q, o);
    float inv = rsqrtf(q * (1.0f / 128.0f) + eps);
    size_t base = (size_t)row * 128;
    float y0 = d0 * inv * g[lane]      + b[lane];
    float y1 = d1 * inv * g[lane + 32] + b[lane + 32];
    float y2 = d2 * inv * g[lane + 64] + b[lane + 64];
    float y3 = d3 * inv * g[lane + 96] + b[lane + 96];
    __nv_bfloat16 hi, lo;
    bf16split(y0, &hi, &lo); g_hh[base + lane]      = hi; g_hl[base + lane]      = lo;
    bf16split(y1, &hi, &lo); g_hh[base + lane + 32] = hi; g_hl[base + lane + 32] = lo;
    bf16split(y2, &hi, &lo); g_hh[base + lane + 64] = hi; g_hl[base + lane + 64] = lo;
    bf16split(y3, &hi, &lo); g_hh[base + lane + 96] = hi; g_hl[base + lane + 96] = lo;
}

// ============================================================================
// mma.sync GEMM with cp.async double-buffering.
// 64x64 tile, 256 threads = 8 warps (2m x 4n), warp tile 32x16, K-chunk 32.
// ============================================================================
#define AKP 40
#define BNP 72
__global__ __launch_bounds__(256) void mm_mma(
    const __nv_bfloat16* __restrict__ Ah, const __nv_bfloat16* __restrict__ Al,
    const __nv_bfloat16* __restrict__ Wimg, int N, int K,
    const float* __restrict__ bias,
    const float* __restrict__ res, int ldr,
    float* __restrict__ outf, int ldo,
    __nv_bfloat16* __restrict__ oh, __nv_bfloat16* __restrict__ ol, int ldp,
    int relu)
{
    __shared__ __nv_bfloat16 sA[2][2][64 * AKP];   // [stage][hi/lo]
    __shared__ __nv_bfloat16 sB[2][2][32 * BNP];

    int tid = threadIdx.x, lane = tid & 31, wid = tid >> 5;
    int m0 = blockIdx.y * 64, n0 = blockIdx.x * 64;
    int wm = (wid >> 2) * 32, wn = (wid & 3) * 16;

    const __nv_bfloat16* Wh = Wimg;
    const __nv_bfloat16* Wl = Wimg + (size_t)N * K;

    float acc[2][2][4];
    #pragma unroll
    for (int mt = 0; mt < 2; mt++)
        #pragma unroll
        for (int nt = 0; nt < 2; nt++)
            #pragma unroll
            for (int c = 0; c < 4; c++) acc[mt][nt][c] = 0.0f;

    uint32_t sA_b[2][2], sB_b[2][2];
    #pragma unroll
    for (int s = 0; s < 2; s++)
        #pragma unroll
        for (int p = 0; p < 2; p++) {
            sA_b[s][p] = smem_u32(sA[s][p]);
            sB_b[s][p] = smem_u32(sB[s][p]);
        }

    // single-shot load mapping: 256 threads cover A(64x32) and B(32x64)
    int ar0 = tid >> 2, ac0 = (tid & 3) * 8;
    int br0 = tid >> 3, bc0 = (tid & 7) * 8;

    int la_row = lane & 15, la_col = (lane >> 4) * 8;
    int lb_row = lane & 15;

    int nch = K >> 5;

    // prefetch chunk 0 into stage 0
    {
        cp16(sA_b[0][0] + (uint32_t)(ar0 * AKP + ac0) * 2,
             Ah + (size_t)(m0 + ar0) * K + ac0);
        cp16(sA_b[0][1] + (uint32_t)(ar0 * AKP + ac0) * 2,
             Al + (size_t)(m0 + ar0) * K + ac0);
        cp16(sB_b[0][0] + (uint32_t)(br0 * BNP + bc0) * 2,
             Wh + (size_t)br0 * N + n0 + bc0);
        cp16(sB_b[0][1] + (uint32_t)(br0 * BNP + bc0) * 2,
             Wl + (size_t)br0 * N + n0 + bc0);
        CP_COMMIT();
    }

    for (int ch = 0; ch < nch; ch++) {
        int st = ch & 1;
        bool more = (ch + 1 < nch);
        if (more) {
            int k0 = (ch + 1) << 5;
            int s2 = st ^ 1;
            cp16(sA_b[s2][0] + (uint32_t)(ar0 * AKP + ac0) * 2,
                 Ah + (size_t)(m0 + ar0) * K + k0 + ac0);
            cp16(sA_b[s2][1] + (uint32_t)(ar0 * AKP + ac0) * 2,
                 Al + (size_t)(m0 + ar0) * K + k0 + ac0);
            cp16(sB_b[s2][0] + (uint32_t)(br0 * BNP + bc0) * 2,
                 Wh + (size_t)(k0 + br0) * N + n0 + bc0);
            cp16(sB_b[s2][1] + (uint32_t)(br0 * BNP + bc0) * 2,
                 Wl + (size_t)(k0 + br0) * N + n0 + bc0);
            CP_COMMIT();
            cp_wait<1>();
        } else {
            cp_wait<0>();
        }
        __syncthreads();

        #pragma unroll
        for (int ks = 0; ks < 2; ks++) {
            int kb = ks * 16;
            uint32_t bH[2][2], bL[2][2];
            #pragma unroll
            for (int nt = 0; nt < 2; nt++) {
                uint32_t boff = (uint32_t)((kb + lb_row) * BNP + wn + nt * 8) * 2;
                ldmBt(bH[nt], sB_b[st][0] + boff);
                ldmBt(bL[nt], sB_b[st][1] + boff);
            }
            #pragma unroll
            for (int mt = 0; mt < 2; mt++) {
                uint32_t aoff = (uint32_t)((wm + mt * 16 + la_row) * AKP + kb + la_col) * 2;
                uint32_t aH[4], aL[4];
                ldmA(aH, sA_b[st][0] + aoff);
                ldmA(aL, sA_b[st][1] + aoff);
                #pragma unroll
                for (int nt = 0; nt < 2; nt++) {
                    mma16816(acc[mt][nt], aH, bH[nt]);
                    mma16816(acc[mt][nt], aH, bL[nt]);
                    mma16816(acc[mt][nt], aL, bH[nt]);
                }
            }
        }
        __syncthreads();
    }

    int g = lane >> 2, tg = lane & 3;
    #pragma unroll
    for (int mt = 0; mt < 2; mt++) {
        #pragma unroll
        for (int nt = 0; nt < 2; nt++) {
            int col = n0 + wn + nt * 8 + tg * 2;
            #pragma unroll
            for (int half = 0; half < 2; half++) {
                int row = m0 + wm + mt * 16 + g + half * 8;
                float v0 = acc[mt][nt][half * 2];
                float v1 = acc[mt][nt][half * 2 + 1];
                if (bias) { v0 += bias[col]; v1 += bias[col + 1]; }
                if (res) {
                    v0 += res[(size_t)row * ldr + col];
                    v1 += res[(size_t)row * ldr + col + 1];
                }
                if (relu) { v0 = fmaxf(v0, 0.0f); v1 = fmaxf(v1, 0.0f); }
                if (outf) {
                    outf[(size_t)row * ldo + col]     = v0;
                    outf[(size_t)row * ldo + col + 1] = v1;
                }
                if (oh) {
                    __nv_bfloat16 hi, lo;
                    bf16split(v0, &hi, &lo);
                    oh[(size_t)row * ldp + col] = hi;
                    ol[(size_t)row * ldp + col] = lo;
                    bf16split(v1, &hi, &lo);
                    oh[(size_t)row * ldp + col + 1] = hi;
                    ol[(size_t)row * ldp + col + 1] = lo;
                }
            }
        }
    }
}

// ============================================================================
// fused attention v4 — 2 query rows per CTA; no partial buffer (per-thread AV)
// grid (32, 64). 256 threads. smem ~72KB -> 3 CTAs/SM.
// ============================================================================
#define ATTN_SMEM_FLOATS (16384 + 512 + 512 + 256 + 256 + 128)
__global__ __launch_bounds__(256) void attn_kernel(
    const float* __restrict__ edge,
    const void* __restrict__ mask,
    const float* __restrict__ be_l,
    float* __restrict__ attn_out, int write_attn,
    int layer)
{
    extern __shared__ float sm[];
    float* s_e    = sm;                 // 2 x 8192: edge tiles for i0, i1
    float* s_q    = s_e + 16384;        // 2 x 256
    float* s_qe   = s_q + 512;          // 2 x 256
    float* s_sc   = s_qe + 512;         // 2 x 128
    float* s_att  = s_sc + 256;         // 2 x 128
    float* s_be   = s_att + 256;        // 128

    int b = blockIdx.y, i0 = blockIdx.x * 2;
    int t = threadIdx.x, lane = t & 31, w = t >> 5;
    int mode = g_mask_mode;
    size_t qrow0 = (size_t)(b * 64 + i0) * 1024;

    const float4* esrc = (const float4*)(edge + ((size_t)(b * 64 + i0)) * 8192);
    #pragma unroll
    for (int r = 0; r < 16; r++)
        ((float4*)s_e)[t + r * 256] = esrc[t + r * 256];
    s_q [t]       = g_qkv[qrow0 + t];
    s_q [256 + t] = g_qkv[qrow0 + 1024 + t];
    s_qe[t]       = g_qkv[qrow0 + 768 + t];
    s_qe[256 + t] = g_qkv[qrow0 + 1024 + 768 + t];
    if (t < 128) s_be[t] = be_l[t];
    __syncthreads();

    // scores: warp w: h = w>>2, j = (w&3)*16 + oo; both i per k-load
    {
        int h = w >> 2;
        float4 q0  = *(float4*)&s_q [h * 128 + lane * 4];
        float4 q1  = *(float4*)&s_q [256 + h * 128 + lane * 4];
        float4 qe0 = *(float4*)&s_qe[h * 128 + lane * 4];
        float4 qe1 = *(float4*)&s_qe[256 + h * 128 + lane * 4];
        float4 be4 = *(float4*)&s_be[lane * 4];
        float qb0 = q0.x*be4.x + q0.y*be4.y + q0.z*be4.z + q0.w*be4.w;
        float qb1 = q1.x*be4.x + q1.y*be4.y + q1.z*be4.z + q1.w*be4.w;
        #pragma unroll
        for (int off = 16; off; off >>= 1) {
            qb0 += __shfl_xor_sync(0xffffffffu, qb0, off);
            qb1 += __shfl_xor_sync(0xffffffffu, qb1, off);
        }

        #pragma unroll
        for (int oo = 0; oo < 16; oo++) {
            int j = (w & 3) * 16 + oo;
            float4 k4 = *(const float4*)(g_qkv + (size_t)(b * 64 + j) * 1024
                                         + 256 + h * 128 + lane * 4);
            float4 e0 = *(float4*)&s_e[j * 128 + lane * 4];
            float4 e1 = *(float4*)&s_e[8192 + j * 128 + lane * 4];
            float d0 = q0.x*k4.x + q0.y*k4.y + q0.z*k4.z + q0.w*k4.w
                     + qe0.x*e0.x + qe0.y*e0.y + qe0.z*e0.z + qe0.w*e0.w;
            float d1 = q1.x*k4.x + q1.y*k4.y + q1.z*k4.z + q1.w*k4.w
                     + qe1.x*e1.x + qe1.y*e1.y + qe1.z*e1.z + qe1.w*e1.w;
            #pragma unroll
            for (int off = 16; off; off >>= 1) {
                d0 += __shfl_xor_sync(0xffffffffu, d0, off);
                d1 += __shfl_xor_sync(0xffffffffu, d1, off);
            }
            if (lane == 0) {
                s_sc[h * 64 + j]       = d0 + qb0;
                s_sc[128 + h * 64 + j] = d1 + qb1;
            }
        }
    }
    __syncthreads();

    // masked softmax: warps 0..3 -> (ii = w>>1, h = w&1)
    if (w < 4) {
        const float invT = 0.08838834764831843f;  // 1/sqrt(128)
        int ii = w >> 1, h = w & 1;
        int iabs = i0 + ii;
        size_t mbase = ((size_t)(b * 64 + iabs)) * 64;
        float v0 = s_sc[ii * 128 + h * 64 + lane]      * invT;
        float v1 = s_sc[ii * 128 + h * 64 + lane + 32] * invT;
        if (mask_at(mask, mbase + lane,      mode)) v0 = 1e-10f;
        if (mask_at(mask, mbase + lane + 32, mode)) v1 = 1e-10f;
        float mx = fmaxf(v0, v1);
        #pragma unroll
        for (int off = 16; off; off >>= 1)
            mx = fmaxf(mx, __shfl_xor_sync(0xffffffffu, mx, off));
        float e0 = expf(v0 - mx), e1 = expf(v1 - mx);
        float s = e0 + e1;
        #pragma unroll
        for (int off = 16; off; off >>= 1)
            s += __shfl_xor_sync(0xffffffffu, s, off);
        float inv = 1.0f / s;
        e0 *= inv; e1 *= inv;
        s_att[ii * 128 + h * 64 + lane]      = e0;
        s_att[ii * 128 + h * 64 + lane + 32] = e1;
        if (write_attn) {
            float* ap = attn_out +
                ((((size_t)layer * NHH + h) * BB + b) * NNODE + iabs) * NNODE;
            ap[lane]      = e0;
            ap[lane + 32] = e1;
        }
    }
    __syncthreads();

    // AV: per-thread output (sel, h, d0); serial j loop; both i
    {
        int sel = t >> 7, h = (t >> 6) & 1, d0 = (t & 63) * 2;
        #pragma unroll
        for (int ii = 0; ii < 2; ii++) {
            float2 acc = make_float2(0.0f, 0.0f);
            const float* att = s_att + ii * 128 + h * 64;
            if (sel == 0) {
                const float* vbase = g_qkv + (size_t)(b * 64) * 1024 + 512 + h * 128 + d0;
                #pragma unroll 8
                for (int j = 0; j < 64; j++) {
                    float a = att[j];
                    float2 x = *(const float2*)(vbase + (size_t)j * 1024);
                    acc.x += a * x.x; acc.y += a * x.y;
                }
            } else {
                const float* ebase = s_e + ii * 8192 + d0;
                #pragma unroll 8
                for (int j = 0; j < 64; j++) {
                    float a = att[j];
                    float2 x = *(const float2*)(ebase + j * 128);
                    acc.x += a * x.x; acc.y += a * x.y;
                }
            }
            size_t mo = ((size_t)(b * 64 + i0 + ii)) * 512 + sel * 256 + h * 128 + d0;
            __nv_bfloat16 hi, lo;
            bf16split(acc.x, &hi, &lo); g_mhah[mo]     = hi; g_mhal[mo]     = lo;
            bf16split(acc.y, &hi, &lo); g_mhah[mo + 1] = hi; g_mhal[mo + 1] = lo;
        }
    }
}

// ---------------- final mean over nodes ----------------
__global__ void mean_kernel(float* __restrict__ out)
{
    int b = blockIdx.x, d = threadIdx.x;
    float s = 0.0f;
    for (int n = 0; n < 64; n++) s += g_emb[(size_t)(b * 64 + n) * 128 + d];
    out[b * 128 + d] = s * (1.0f / 64.0f);
}

// ============================================================================
// host
// ============================================================================
extern "C" void kernel_launch(void* const* d_in, const int* in_sizes, int n_in,
                              void* d_out, int out_size)
{
    if (n_in < 21) return;
    bool dict = (in_sizes[3] == BB * NNODE * NNODE);

    const float *nf, *st, *ef, *Wn, *bn, *We, *be, *l1g, *l1b,
                *Wq, *Wk, *Wv, *Wo, *bo, *l2g, *l2b, *W1, *b1, *W2, *b2;
    const void* mask;

    if (dict) {
        nf  = (const float*)d_in[0];  st  = (const float*)d_in[1];
        ef  = (const float*)d_in[2];  mask = d_in[3];
        Wn  = (const float*)d_in[4];  bn  = (const float*)d_in[5];
        We  = (const float*)d_in[6];  be  = (const float*)d_in[7];
        l1g = (const float*)d_in[8];  l1b = (const float*)d_in[9];
        Wq  = (const float*)d_in[10]; Wk  = (const float*)d_in[11];
        Wv  = (const float*)d_in[12]; Wo  = (const float*)d_in[13];
        bo  = (const float*)d_in[14]; l2g = (const float*)d_in[15];
        l2b = (const float*)d_in[16]; W1  = (const float*)d_in[17];
        b1  = (const float*)d_in[18]; W2  = (const float*)d_in[19];
        b2  = (const float*)d_in[20];
    } else {
        nf  = (const float*)d_in[0];  st  = (const float*)d_in[1];
        ef  = (const float*)d_in[2];
        Wn  = (const float*)d_in[3];  bn  = (const float*)d_in[4];
        We  = (const float*)d_in[5];  be  = (const float*)d_in[6];
        l1g = (const float*)d_in[7];  l1b = (const float*)d_in[8];
        Wq  = (const float*)d_in[9];  Wk  = (const float*)d_in[10];
        Wv  = (const float*)d_in[11]; Wo  = (const float*)d_in[12];
        bo  = (const float*)d_in[13]; l2g = (const float*)d_in[14];
        l2b = (const float*)d_in[15]; W1  = (const float*)d_in[16];
        b1  = (const float*)d_in[17]; W2  = (const float*)d_in[18];
        b2  = (const float*)d_in[19]; mask = d_in[20];
    }

    float *p_emb, *p_cvec, *p_qkv;
    __nv_bfloat16 *p_x0h, *p_x0l, *p_hh, *p_hl, *p_mhah, *p_mhal, *p_ffh, *p_ffl;
    __nv_bfloat16 *p_WnImg, *p_WprojImg, *p_WbigImg, *p_W1Img, *p_W2Img;
    cudaGetSymbolAddress((void**)&p_emb,   g_emb);
    cudaGetSymbolAddress((void**)&p_cvec,  g_cvec);
    cudaGetSymbolAddress((void**)&p_x0h,   g_x0h);
    cudaGetSymbolAddress((void**)&p_x0l,   g_x0l);
    cudaGetSymbolAddress((void**)&p_hh,    g_hh);
    cudaGetSymbolAddress((void**)&p_hl,    g_hl);
    cudaGetSymbolAddress((void**)&p_mhah,  g_mhah);
    cudaGetSymbolAddress((void**)&p_mhal,  g_mhal);
    cudaGetSymbolAddress((void**)&p_ffh,   g_ffh);
    cudaGetSymbolAddress((void**)&p_ffl,   g_ffl);
    cudaGetSymbolAddress((void**)&p_qkv,   g_qkv);
    cudaGetSymbolAddress((void**)&p_WnImg,   g_WnImg);
    cudaGetSymbolAddress((void**)&p_WprojImg, g_WprojImg);
    cudaGetSymbolAddress((void**)&p_WbigImg,  g_WbigImg);
    cudaGetSymbolAddress((void**)&p_W1Img,    g_W1Img);
    cudaGetSymbolAddress((void**)&p_W2Img,    g_W2Img);

    const int ATTN_SMEM = ATTN_SMEM_FLOATS * 4;
    cudaFuncSetAttribute(attn_kernel, cudaFuncAttributeMaxDynamicSharedMemorySize, ATTN_SMEM);

    float* out = (float*)d_out;
    size_t need_attn = (size_t)BB * DD + (size_t)LLAYERS * NHH * BB * NNODE * NNODE;
    int write_attn = ((size_t)out_size >= need_attn) ? 1 : 0;
    float* attn_base = out + BB * DD;

    fused_prep<<<PREP_BLOCKS, 256>>>(Wn, Wq, Wk, Wv, We, Wo, W1, W2, be, bo);
    detect_mask_kernel<<<1, 256>>>((const unsigned char*)mask);
    concat_kernel<<<(ROWS * 64 + 255) / 256, 256>>>(nf, st);
    // 4th launch: Wn GEMM (stays in the ncu capture slot for A/B comparison)
    mm_mma<<<dim3(2, 64), 256>>>(p_x0h, p_x0l, p_WnImg, 128, 256,
        bn, nullptr, 0, p_emb, 128, nullptr, nullptr, 0, 0);

    for (int l = 0; l < LLAYERS; l++) {
        const float* be_l = be + (size_t)l * 128;
        ln_kernel<<<512, 256>>>(p_emb, l1g + l * 128, l1b + l * 128, 1e-5f);
        mm_mma<<<dim3(16, 64), 256>>>(p_hh, p_hl,
            p_WprojImg + (size_t)l * 2 * 128 * 1024, 1024, 128,
            nullptr, nullptr, 0, p_qkv, 1024, nullptr, nullptr, 0, 0);

        attn_kernel<<<dim3(32, 64), 256, ATTN_SMEM>>>(ef, mask, be_l,
                                                      attn_base, write_attn, l);

        mm_mma<<<dim3(2, 64), 256>>>(p_mhah, p_mhal,
            p_WbigImg + (size_t)l * 2 * 512 * 128, 128, 512,
            p_cvec + l * 128, p_emb, 128, p_emb, 128, nullptr, nullptr, 0, 0);

        ln_kernel<<<512, 256>>>(p_emb, l2g + l * 128, l2b + l * 128, 1e-6f);
        mm_mma<<<dim3(8, 64), 256>>>(p_hh, p_hl,
            p_W1Img + (size_t)l * 2 * 128 * 512, 512, 128,
            b1 + (size_t)l * 512, nullptr, 0, nullptr, 0, p_ffh, p_ffl, 512, 1);
        mm_mma<<<dim3(2, 64), 256>>>(p_ffh, p_ffl,
            p_W2Img + (size_t)l * 2 * 512 * 128, 128, 512,
            b2 + (size_t)l * 128, p_emb, 128, p_emb, 128, nullptr, nullptr, 0, 0);
    }

    mean_kernel<<<BB, 128>>>(out);
}

// round 11
// speedup vs baseline: 1.0504x; 1.0504x over previous
#include <cuda_runtime.h>
#include <cuda_bf16.h>
#include <math.h>
#include <stdint.h>

// Problem dims
#define BB 64
#define NNODE 64
#define DD 128
#define NHH 2
#define LLAYERS 2
#define ROWS (BB*NNODE)          // 4096

// ============================================================================
// Helpers
// ============================================================================
__device__ __forceinline__ uint32_t smem_u32(const void* p) {
    uint32_t a;
    asm("{ .reg .u64 t; cvta.to.shared.u64 t, %1; cvt.u32.u64 %0, t; }"
        : "=r"(a) : "l"(p));
    return a;
}

__device__ __forceinline__ void ldmA(uint32_t* a, uint32_t addr) {
    asm volatile("ldmatrix.sync.aligned.m8n8.x4.shared.b16 {%0,%1,%2,%3}, [%4];"
        : "=r"(a[0]), "=r"(a[1]), "=r"(a[2]), "=r"(a[3]) : "r"(addr));
}
__device__ __forceinline__ void ldmBt(uint32_t* b, uint32_t addr) {
    asm volatile("ldmatrix.sync.aligned.m8n8.x2.trans.shared.b16 {%0,%1}, [%2];"
        : "=r"(b[0]), "=r"(b[1]) : "r"(addr));
}
__device__ __forceinline__ void mma16816(float* d, const uint32_t* a, const uint32_t* b) {
    asm volatile("mma.sync.aligned.m16n8k16.row.col.f32.bf16.bf16.f32 "
        "{%0,%1,%2,%3}, {%4,%5,%6,%7}, {%8,%9}, {%0,%1,%2,%3};"
        : "+f"(d[0]), "+f"(d[1]), "+f"(d[2]), "+f"(d[3])
        : "r"(a[0]), "r"(a[1]), "r"(a[2]), "r"(a[3]), "r"(b[0]), "r"(b[1]));
}
__device__ __forceinline__ void cp16(uint32_t saddr, const void* gptr) {
    asm volatile("cp.async.cg.shared.global [%0], [%1], 16;"
        :: "r"(saddr), "l"(gptr));
}
#define CP_COMMIT() asm volatile("cp.async.commit_group;" ::: "memory")
template <int N>
__device__ __forceinline__ void cp_wait() {
    asm volatile("cp.async.wait_group %0;" :: "n"(N) : "memory");
}

__device__ __forceinline__ void bf16split(float v, __nv_bfloat16* hi, __nv_bfloat16* lo) {
    __nv_bfloat16 h = __float2bfloat16(v);
    *hi = h;
    *lo = __float2bfloat16(v - __bfloat162float(h));
}

// ============================================================================
// Scratch (device globals; no allocation)
// ============================================================================
__device__ __nv_bfloat16 g_x0h [ROWS*256];
__device__ __nv_bfloat16 g_x0l [ROWS*256];
__device__ float         g_emb [ROWS*128];
__device__ __nv_bfloat16 g_hh  [ROWS*128];
__device__ __nv_bfloat16 g_hl  [ROWS*128];
__device__ float         g_qkv [ROWS*1024];
__device__ __nv_bfloat16 g_mhah[ROWS*512];
__device__ __nv_bfloat16 g_mhal[ROWS*512];
__device__ __nv_bfloat16 g_ffh [ROWS*512];
__device__ __nv_bfloat16 g_ffl [ROWS*512];
__device__ float         g_cvec[LLAYERS*128];
__device__ int           g_mask_mode;

// Weight images, natural [K][N] bf16, hi plane then lo plane
__device__ __nv_bfloat16 g_WnImg  [2*256*128];
__device__ __nv_bfloat16 g_WprojImg[LLAYERS][2*128*1024];
__device__ __nv_bfloat16 g_WbigImg [LLAYERS][2*512*128];
__device__ __nv_bfloat16 g_W1Img   [LLAYERS][2*128*512];
__device__ __nv_bfloat16 g_W2Img   [LLAYERS][2*512*128];

// ============================================================================
// mask dtype detection (parallel)
// ============================================================================
__global__ void detect_mask_kernel(const unsigned char* __restrict__ m)
{
    __shared__ int cnt[2];
    if (threadIdx.x < 2) cnt[threadIdx.x] = 0;
    __syncthreads();
    int u8 = 0, f32 = 0;
    for (int i = threadIdx.x; i < 4096; i += 256) {
        unsigned char v = m[i];
        if (v) {
            int r = i & 3;
            if (r == 1) u8++;
            else if (r == 3) f32++;
        }
    }
    if (u8)  atomicAdd(&cnt[0], u8);
    if (f32) atomicAdd(&cnt[1], f32);
    __syncthreads();
    if (threadIdx.x == 0)
        g_mask_mode = cnt[0] ? 0 : (cnt[1] ? 2 : 1);
}
__device__ __forceinline__ bool mask_at(const void* mp, size_t idx, int mode)
{
    if (mode == 0) return ((const unsigned char*)mp)[idx] != 0;
    if (mode == 1) return ((const int*)mp)[idx] != 0;
    return ((const float*)mp)[idx] != 0.0f;
}

// ============================================================================
// Fused prologue: ALL weight-image prep in one kernel (blockIdx dispatch)
// ============================================================================
#define PREP_BLOCKS (128 + 768 + 256 + 256 + 256 + 512 + 512 + 1)
__global__ void fused_prep(const float* __restrict__ Wn, const float* __restrict__ Wq,
                           const float* __restrict__ Wk, const float* __restrict__ Wv,
                           const float* __restrict__ We, const float* __restrict__ Wo,
                           const float* __restrict__ W1, const float* __restrict__ W2,
                           const float* __restrict__ be, const float* __restrict__ bo)
{
    int blk = blockIdx.x, tid = threadIdx.x;
    __nv_bfloat16 hi, lo;

    if (blk < 128) {
        int t = blk * 256 + tid;
        bf16split(Wn[t], &hi, &lo);
        g_WnImg[t] = hi; g_WnImg[32768 + t] = lo;
        return;
    }
    blk -= 128;
    if (blk < 768) {
        int idx = blk * 256 + tid;
        int l = idx / 98304, r = idx % 98304;
        int k = r / 768, n = r % 768;
        const float* W = (n < 256) ? Wq : (n < 512 ? Wk : Wv);
        float v = W[(size_t)l * 32768 + (size_t)k * 256 + (n & 255)];
        bf16split(v, &hi, &lo);
        g_WprojImg[l][(size_t)k * 1024 + n]          = hi;
        g_WprojImg[l][131072 + (size_t)k * 1024 + n] = lo;
        return;
    }
    blk -= 768;
    if (blk < 256) {
        int idx = blk * 256 + tid;
        int l = idx >> 15, r = idx & 32767;
        int h = r >> 14, r2 = r & 16383;
        int e = r2 >> 7, d = r2 & 127;
        const float* wq = Wq + (size_t)l * 32768 + (size_t)d * 256 + h * 128;
        const float* we = We + (size_t)l * 16384 + (size_t)e * 128;
        float acc = 0.0f;
        #pragma unroll 8
        for (int c = 0; c < 128; c++) acc += wq[c] * we[c];
        size_t o = (size_t)d * 1024 + 768 + h * 128 + e;
        bf16split(acc, &hi, &lo);
        g_WprojImg[l][o] = hi; g_WprojImg[l][131072 + o] = lo;
        return;
    }
    blk -= 256;
    if (blk < 256) {
        int idx = blk * 256 + tid;
        int l = idx >> 15, t2 = idx & 32767;
        bf16split(Wo[(size_t)l * 32768 + t2], &hi, &lo);
        g_WbigImg[l][t2] = hi; g_WbigImg[l][65536 + t2] = lo;
        return;
    }
    blk -= 256;
    if (blk < 256) {
        int idx = blk * 256 + tid;
        int l = idx >> 15, r = idx & 32767;
        int h = r >> 14, r2 = r & 16383;
        int f = r2 >> 7, n = r2 & 127;
        const float* we = We + (size_t)l * 16384 + (size_t)f * 128;
        const float* wo = Wo + (size_t)l * 32768 + (size_t)(h * 128) * 128 + n;
        float acc = 0.0f;
        #pragma unroll 8
        for (int e = 0; e < 128; e++) acc += we[e] * wo[(size_t)e * 128];
        size_t o = (size_t)(256 + h * 128 + f) * 128 + n;
        bf16split(acc, &hi, &lo);
        g_WbigImg[l][o] = hi; g_WbigImg[l][65536 + o] = lo;
        return;
    }
    blk -= 256;
    if (blk < 512) {
        int idx = blk * 256 + tid;
        int l = idx >> 16, t2 = idx & 65535;
        bf16split(W1[(size_t)l * 65536 + t2], &hi, &lo);
        g_W1Img[l][t2] = hi; g_W1Img[l][65536 + t2] = lo;
        return;
    }
    blk -= 512;
    if (blk < 512) {
        int idx = blk * 256 + tid;
        int l = idx >> 16, t2 = idx & 65535;
        bf16split(W2[(size_t)l * 65536 + t2], &hi, &lo);
        g_W2Img[l][t2] = hi; g_W2Img[l][65536 + t2] = lo;
        return;
    }
    blk -= 512;
    {
        int l = tid >> 7, d = tid & 127;
        float acc = bo[l * 128 + d];
        const float* wo = Wo + (size_t)l * 32768;
        const float* bel = be + l * 128;
        for (int r = 0; r < 256; r++) acc += bel[r & 127] * wo[(size_t)r * 128 + d];
        g_cvec[l * 128 + d] = acc;
    }
}

// ============================================================================
// concat(node_feat, stpe) -> bf16 pairs [4096,256]
// ============================================================================
__global__ void concat_kernel(const float* __restrict__ nf, const float* __restrict__ st)
{
    int t = blockIdx.x * blockDim.x + threadIdx.x;
    if (t < ROWS * 64) {
        int row = t >> 6, c4 = t & 63;
        float4 val = (c4 < 32) ? ((const float4*)nf)[row * 32 + c4]
                               : ((const float4*)st)[row * 32 + (c4 - 32)];
        size_t o = (size_t)row * 256 + c4 * 4;
        float vv[4] = {val.x, val.y, val.z, val.w};
        #pragma unroll
        for (int j = 0; j < 4; j++) {
            __nv_bfloat16 hi, lo; bf16split(vv[j], &hi, &lo);
            g_x0h[o + j] = hi; g_x0l[o + j] = lo;
        }
    }
}

// ============================================================================
// LayerNorm -> bf16 pairs
// ============================================================================
__global__ void ln_kernel(const float* __restrict__ x,
                          const float* __restrict__ g, const float* __restrict__ b,
                          float eps)
{
    int row  = blockIdx.x * 8 + (threadIdx.x >> 5);
    int lane = threadIdx.x & 31;
    const float* xr = x + (size_t)row * 128;
    float v0 = xr[lane], v1 = xr[lane + 32], v2 = xr[lane + 64], v3 = xr[lane + 96];
    float s = v0 + v1 + v2 + v3;
    #pragma unroll
    for (int o = 16; o; o >>= 1) s += __shfl_xor_sync(0xffffffffu, s, o);
    float mu = s * (1.0f / 128.0f);
    float d0 = v0 - mu, d1 = v1 - mu, d2 = v2 - mu, d3 = v3 - mu;
    float q = d0*d0 + d1*d1 + d2*d2 + d3*d3;
    #pragma unroll
    for (int o = 16; o; o >>= 1) q += __shfl_xor_sync(0xffffffffu, q, o);
    float inv = rsqrtf(q * (1.0f / 128.0f) + eps);
    size_t base = (size_t)row * 128;
    float y0 = d0 * inv * g[lane]      + b[lane];
    float y1 = d1 * inv * g[lane + 32] + b[lane + 32];
    float y2 = d2 * inv * g[lane + 64] + b[lane + 64];
    float y3 = d3 * inv * g[lane + 96] + b[lane + 96];
    __nv_bfloat16 hi, lo;
    bf16split(y0, &hi, &lo); g_hh[base + lane]      = hi; g_hl[base + lane]      = lo;
    bf16split(y1, &hi, &lo); g_hh[base + lane + 32] = hi; g_hl[base + lane + 32] = lo;
    bf16split(y2, &hi, &lo); g_hh[base + lane + 64] = hi; g_hl[base + lane + 64] = lo;
    bf16split(y3, &hi, &lo); g_hh[base + lane + 96] = hi; g_hl[base + lane + 96] = lo;
}

// ============================================================================
// mma.sync GEMM with cp.async double-buffering.
// 64x64 tile, 256 threads = 8 warps (2m x 4n), warp tile 32x16, K-chunk 32.
// Three INDEPENDENT accumulators per tile (hi*hi, hi*lo, lo*hi) -> 12
// independent HMMA chains per warp; summed in epilogue.
// ============================================================================
#define AKP 40
#define BNP 72
__global__ __launch_bounds__(256) void mm_mma(
    const __nv_bfloat16* __restrict__ Ah, const __nv_bfloat16* __restrict__ Al,
    const __nv_bfloat16* __restrict__ Wimg, int N, int K,
    const float* __restrict__ bias,
    const float* __restrict__ res, int ldr,
    float* __restrict__ outf, int ldo,
    __nv_bfloat16* __restrict__ oh, __nv_bfloat16* __restrict__ ol, int ldp,
    int relu)
{
    __shared__ __nv_bfloat16 sA[2][2][64 * AKP];   // [stage][hi/lo]
    __shared__ __nv_bfloat16 sB[2][2][32 * BNP];

    int tid = threadIdx.x, lane = tid & 31, wid = tid >> 5;
    int m0 = blockIdx.y * 64, n0 = blockIdx.x * 64;
    int wm = (wid >> 2) * 32, wn = (wid & 3) * 16;

    const __nv_bfloat16* Wh = Wimg;
    const __nv_bfloat16* Wl = Wimg + (size_t)N * K;

    float accA[2][2][4], accB[2][2][4], accC[2][2][4];
    #pragma unroll
    for (int mt = 0; mt < 2; mt++)
        #pragma unroll
        for (int nt = 0; nt < 2; nt++)
            #pragma unroll
            for (int c = 0; c < 4; c++) {
                accA[mt][nt][c] = 0.0f;
                accB[mt][nt][c] = 0.0f;
                accC[mt][nt][c] = 0.0f;
            }

    uint32_t sA_b[2][2], sB_b[2][2];
    #pragma unroll
    for (int s = 0; s < 2; s++)
        #pragma unroll
        for (int p = 0; p < 2; p++) {
            sA_b[s][p] = smem_u32(sA[s][p]);
            sB_b[s][p] = smem_u32(sB[s][p]);
        }

    // single-shot load mapping: 256 threads cover A(64x32) and B(32x64)
    int ar0 = tid >> 2, ac0 = (tid & 3) * 8;
    int br0 = tid >> 3, bc0 = (tid & 7) * 8;

    int la_row = lane & 15, la_col = (lane >> 4) * 8;
    int lb_row = lane & 15;

    int nch = K >> 5;

    // prefetch chunk 0 into stage 0
    {
        cp16(sA_b[0][0] + (uint32_t)(ar0 * AKP + ac0) * 2,
             Ah + (size_t)(m0 + ar0) * K + ac0);
        cp16(sA_b[0][1] + (uint32_t)(ar0 * AKP + ac0) * 2,
             Al + (size_t)(m0 + ar0) * K + ac0);
        cp16(sB_b[0][0] + (uint32_t)(br0 * BNP + bc0) * 2,
             Wh + (size_t)br0 * N + n0 + bc0);
        cp16(sB_b[0][1] + (uint32_t)(br0 * BNP + bc0) * 2,
             Wl + (size_t)br0 * N + n0 + bc0);
        CP_COMMIT();
    }

    for (int ch = 0; ch < nch; ch++) {
        int st = ch & 1;
        bool more = (ch + 1 < nch);
        if (more) {
            int k0 = (ch + 1) << 5;
            int s2 = st ^ 1;
            cp16(sA_b[s2][0] + (uint32_t)(ar0 * AKP + ac0) * 2,
                 Ah + (size_t)(m0 + ar0) * K + k0 + ac0);
            cp16(sA_b[s2][1] + (uint32_t)(ar0 * AKP + ac0) * 2,
                 Al + (size_t)(m0 + ar0) * K + k0 + ac0);
            cp16(sB_b[s2][0] + (uint32_t)(br0 * BNP + bc0) * 2,
                 Wh + (size_t)(k0 + br0) * N + n0 + bc0);
            cp16(sB_b[s2][1] + (uint32_t)(br0 * BNP + bc0) * 2,
                 Wl + (size_t)(k0 + br0) * N + n0 + bc0);
            CP_COMMIT();
            cp_wait<1>();
        } else {
            cp_wait<0>();
        }
        __syncthreads();

        #pragma unroll
        for (int ks = 0; ks < 2; ks++) {
            int kb = ks * 16;
            uint32_t bH[2][2], bL[2][2];
            #pragma unroll
            for (int nt = 0; nt < 2; nt++) {
                uint32_t boff = (uint32_t)((kb + lb_row) * BNP + wn + nt * 8) * 2;
                ldmBt(bH[nt], sB_b[st][0] + boff);
                ldmBt(bL[nt], sB_b[st][1] + boff);
            }
            #pragma unroll
            for (int mt = 0; mt < 2; mt++) {
                uint32_t aoff = (uint32_t)((wm + mt * 16 + la_row) * AKP + kb + la_col) * 2;
                uint32_t aH[4], aL[4];
                ldmA(aH, sA_b[st][0] + aoff);
                ldmA(aL, sA_b[st][1] + aoff);
                #pragma unroll
                for (int nt = 0; nt < 2; nt++) {
                    mma16816(accA[mt][nt], aH, bH[nt]);
                    mma16816(accB[mt][nt], aH, bL[nt]);
                    mma16816(accC[mt][nt], aL, bH[nt]);
                }
            }
        }
        __syncthreads();
    }

    int g = lane >> 2, tg = lane & 3;
    #pragma unroll
    for (int mt = 0; mt < 2; mt++) {
        #pragma unroll
        for (int nt = 0; nt < 2; nt++) {
            int col = n0 + wn + nt * 8 + tg * 2;
            #pragma unroll
            for (int half = 0; half < 2; half++) {
                int row = m0 + wm + mt * 16 + g + half * 8;
                float v0 = accA[mt][nt][half * 2]     + accB[mt][nt][half * 2]
                         + accC[mt][nt][half * 2];
                float v1 = accA[mt][nt][half * 2 + 1] + accB[mt][nt][half * 2 + 1]
                         + accC[mt][nt][half * 2 + 1];
                if (bias) { v0 += bias[col]; v1 += bias[col + 1]; }
                if (res) {
                    v0 += res[(size_t)row * ldr + col];
                    v1 += res[(size_t)row * ldr + col + 1];
                }
                if (relu) { v0 = fmaxf(v0, 0.0f); v1 = fmaxf(v1, 0.0f); }
                if (outf) {
                    outf[(size_t)row * ldo + col]     = v0;
                    outf[(size_t)row * ldo + col + 1] = v1;
                }
                if (oh) {
                    __nv_bfloat16 hi, lo;
                    bf16split(v0, &hi, &lo);
                    oh[(size_t)row * ldp + col] = hi;
                    ol[(size_t)row * ldp + col] = lo;
                    bf16split(v1, &hi, &lo);
                    oh[(size_t)row * ldp + col + 1] = hi;
                    ol[(size_t)row * ldp + col + 1] = lo;
                }
            }
        }
    }
}

// ============================================================================
// fused attention v3 (R9 version) — 2 query rows per CTA, partial-sum buffer
// grid (32, 64). 256 threads. smem ~105KB -> 2 CTAs/SM.
// ============================================================================
#define ATTN_SMEM_FLOATS (16384 + 8192 + 512 + 512 + 256 + 256 + 128)
__global__ __launch_bounds__(256) void attn_kernel(
    const float* __restrict__ edge,
    const void* __restrict__ mask,
    const float* __restrict__ be_l,
    float* __restrict__ attn_out, int write_attn,
    int layer)
{
    extern __shared__ float sm[];
    float* s_e    = sm;
    float* s_part = s_e + 16384;
    float* s_q    = s_part + 8192;
    float* s_qe   = s_q + 512;
    float* s_sc   = s_qe + 512;
    float* s_att  = s_sc + 256;
    float* s_be   = s_att + 256;

    int b = blockIdx.y, i0 = blockIdx.x * 2;
    int t = threadIdx.x, lane = t & 31, w = t >> 5;
    int mode = g_mask_mode;
    size_t qrow0 = (size_t)(b * 64 + i0) * 1024;

    const float4* esrc = (const float4*)(edge + ((size_t)(b * 64 + i0)) * 8192);
    #pragma unroll
    for (int r = 0; r < 16; r++)
        ((float4*)s_e)[t + r * 256] = esrc[t + r * 256];
    s_q [t]       = g_qkv[qrow0 + t];
    s_q [256 + t] = g_qkv[qrow0 + 1024 + t];
    s_qe[t]       = g_qkv[qrow0 + 768 + t];
    s_qe[256 + t] = g_qkv[qrow0 + 1024 + 768 + t];
    if (t < 128) s_be[t] = be_l[t];
    __syncthreads();

    {
        int h = w >> 2;
        float4 q0  = *(float4*)&s_q [h * 128 + lane * 4];
        float4 q1  = *(float4*)&s_q [256 + h * 128 + lane * 4];
        float4 qe0 = *(float4*)&s_qe[h * 128 + lane * 4];
        float4 qe1 = *(float4*)&s_qe[256 + h * 128 + lane * 4];
        float4 be4 = *(float4*)&s_be[lane * 4];
        float qb0 = q0.x*be4.x + q0.y*be4.y + q0.z*be4.z + q0.w*be4.w;
        float qb1 = q1.x*be4.x + q1.y*be4.y + q1.z*be4.z + q1.w*be4.w;
        #pragma unroll
        for (int off = 16; off; off >>= 1) {
            qb0 += __shfl_xor_sync(0xffffffffu, qb0, off);
            qb1 += __shfl_xor_sync(0xffffffffu, qb1, off);
        }

        #pragma unroll
        for (int oo = 0; oo < 16; oo++) {
            int j = (w & 3) * 16 + oo;
            float4 k4 = *(const float4*)(g_qkv + (size_t)(b * 64 + j) * 1024
                                         + 256 + h * 128 + lane * 4);
            float4 e0 = *(float4*)&s_e[j * 128 + lane * 4];
            float4 e1 = *(float4*)&s_e[8192 + j * 128 + lane * 4];
            float d0 = q0.x*k4.x + q0.y*k4.y + q0.z*k4.z + q0.w*k4.w
                     + qe0.x*e0.x + qe0.y*e0.y + qe0.z*e0.z + qe0.w*e0.w;
            float d1 = q1.x*k4.x + q1.y*k4.y + q1.z*k4.z + q1.w*k4.w
                     + qe1.x*e1.x + qe1.y*e1.y + qe1.z*e1.z + qe1.w*e1.w;
            #pragma unroll
            for (int off = 16; off; off >>= 1) {
                d0 += __shfl_xor_sync(0xffffffffu, d0, off);
                d1 += __shfl_xor_sync(0xffffffffu, d1, off);
            }
            if (lane == 0) {
                s_sc[h * 64 + j]       = d0 + qb0;
                s_sc[128 + h * 64 + j] = d1 + qb1;
            }
        }
    }
    __syncthreads();

    if (w < 4) {
        const float invT = 0.08838834764831843f;
        int ii = w >> 1, h = w & 1;
        int iabs = i0 + ii;
        size_t mbase = ((size_t)(b * 64 + iabs)) * 64;
        float v0 = s_sc[ii * 128 + h * 64 + lane]      * invT;
        float v1 = s_sc[ii * 128 + h * 64 + lane + 32] * invT;
        if (mask_at(mask, mbase + lane,      mode)) v0 = 1e-10f;
        if (mask_at(mask, mbase + lane + 32, mode)) v1 = 1e-10f;
        float mx = fmaxf(v0, v1);
        #pragma unroll
        for (int off = 16; off; off >>= 1)
            mx = fmaxf(mx, __shfl_xor_sync(0xffffffffu, mx, off));
        float e0 = expf(v0 - mx), e1 = expf(v1 - mx);
        float s = e0 + e1;
        #pragma unroll
        for (int off = 16; off; off >>= 1)
            s += __shfl_xor_sync(0xffffffffu, s, off);
        float inv = 1.0f / s;
        e0 *= inv; e1 *= inv;
        s_att[ii * 128 + h * 64 + lane]      = e0;
        s_att[ii * 128 + h * 64 + lane + 32] = e1;
        if (write_attn) {
            float* ap = attn_out +
                ((((size_t)layer * NHH + h) * BB + b) * NNODE + iabs) * NNODE;
            ap[lane]      = e0;
            ap[lane + 32] = e1;
        }
    }
    __syncthreads();

    {
        float a0h0[4] = {}, a0h1[4] = {}, a0e0[4] = {}, a0e1[4] = {};
        float a1h0[4] = {}, a1h1[4] = {}, a1e0[4] = {}, a1e1[4] = {};
        #pragma unroll
        for (int jj = 0; jj < 8; jj++) {
            int j = w + jj * 8;
            const float* vrow = g_qkv + (size_t)(b * 64 + j) * 1024 + 512;
            float4 v0 = *(const float4*)(vrow + lane * 4);
            float4 v1 = *(const float4*)(vrow + 128 + lane * 4);
            float4 e0 = *(float4*)&s_e[j * 128 + lane * 4];
            float4 e1 = *(float4*)&s_e[8192 + j * 128 + lane * 4];
            float w00 = s_att[j],       w01 = s_att[64 + j];
            float w10 = s_att[128 + j], w11 = s_att[192 + j];
            a0h0[0] += w00*v0.x; a0h0[1] += w00*v0.y; a0h0[2] += w00*v0.z; a0h0[3] += w00*v0.w;
            a0h1[0] += w01*v1.x; a0h1[1] += w01*v1.y; a0h1[2] += w01*v1.z; a0h1[3] += w01*v1.w;
            a0e0[0] += w00*e0.x; a0e0[1] += w00*e0.y; a0e0[2] += w00*e0.z; a0e0[3] += w00*e0.w;
            a0e1[0] += w01*e0.x; a0e1[1] += w01*e0.y; a0e1[2] += w01*e0.z; a0e1[3] += w01*e0.w;
            a1h0[0] += w10*v0.x; a1h0[1] += w10*v0.y; a1h0[2] += w10*v0.z; a1h0[3] += w10*v0.w;
            a1h1[0] += w11*v1.x; a1h1[1] += w11*v1.y; a1h1[2] += w11*v1.z; a1h1[3] += w11*v1.w;
            a1e0[0] += w10*e1.x; a1e0[1] += w10*e1.y; a1e0[2] += w10*e1.z; a1e0[3] += w10*e1.w;
            a1e1[0] += w11*e1.x; a1e1[1] += w11*e1.y; a1e1[2] += w11*e1.z; a1e1[3] += w11*e1.w;
        }
        float* pw = s_part + w * 1024;
        *(float4*)&pw[lane * 4]       = make_float4(a0h0[0], a0h0[1], a0h0[2], a0h0[3]);
        *(float4*)&pw[128 + lane * 4] = make_float4(a0h1[0], a0h1[1], a0h1[2], a0h1[3]);
        *(float4*)&pw[256 + lane * 4] = make_float4(a0e0[0], a0e0[1], a0e0[2], a0e0[3]);
        *(float4*)&pw[384 + lane * 4] = make_float4(a0e1[0], a0e1[1], a0e1[2], a0e1[3]);
        *(float4*)&pw[512 + lane * 4] = make_float4(a1h0[0], a1h0[1], a1h0[2], a1h0[3]);
        *(float4*)&pw[640 + lane * 4] = make_float4(a1h1[0], a1h1[1], a1h1[2], a1h1[3]);
        *(float4*)&pw[768 + lane * 4] = make_float4(a1e0[0], a1e0[1], a1e0[2], a1e0[3]);
        *(float4*)&pw[896 + lane * 4] = make_float4(a1e1[0], a1e1[1], a1e1[2], a1e1[3]);
    }
    __syncthreads();

    #pragma unroll
    for (int rep = 0; rep < 4; rep++) {
        int o = t + rep * 256;
        float s = 0.0f;
        #pragma unroll
        for (int ww = 0; ww < 8; ww++) s += s_part[ww * 1024 + o];
        int ii = o >> 9, seg = o & 511;
        size_t mo = ((size_t)(b * 64 + i0 + ii)) * 512 + seg;
        __nv_bfloat16 hi, lo; bf16split(s, &hi, &lo);
        g_mhah[mo] = hi; g_mhal[mo] = lo;
    }
}

// ---------------- final mean over nodes ----------------
__global__ void mean_kernel(float* __restrict__ out)
{
    int b = blockIdx.x, d = threadIdx.x;
    float s = 0.0f;
    for (int n = 0; n < 64; n++) s += g_emb[(size_t)(b * 64 + n) * 128 + d];
    out[b * 128 + d] = s * (1.0f / 64.0f);
}

// ============================================================================
// host
// ============================================================================
extern "C" void kernel_launch(void* const* d_in, const int* in_sizes, int n_in,
                              void* d_out, int out_size)
{
    if (n_in < 21) return;
    bool dict = (in_sizes[3] == BB * NNODE * NNODE);

    const float *nf, *st, *ef, *Wn, *bn, *We, *be, *l1g, *l1b,
                *Wq, *Wk, *Wv, *Wo, *bo, *l2g, *l2b, *W1, *b1, *W2, *b2;
    const void* mask;

    if (dict) {
        nf  = (const float*)d_in[0];  st  = (const float*)d_in[1];
        ef  = (const float*)d_in[2];  mask = d_in[3];
        Wn  = (const float*)d_in[4];  bn  = (const float*)d_in[5];
        We  = (const float*)d_in[6];  be  = (const float*)d_in[7];
        l1g = (const float*)d_in[8];  l1b = (const float*)d_in[9];
        Wq  = (const float*)d_in[10]; Wk  = (const float*)d_in[11];
        Wv  = (const float*)d_in[12]; Wo  = (const float*)d_in[13];
        bo  = (const float*)d_in[14]; l2g = (const float*)d_in[15];
        l2b = (const float*)d_in[16]; W1  = (const float*)d_in[17];
        b1  = (const float*)d_in[18]; W2  = (const float*)d_in[19];
        b2  = (const float*)d_in[20];
    } else {
        nf  = (const float*)d_in[0];  st  = (const float*)d_in[1];
        ef  = (const float*)d_in[2];
        Wn  = (const float*)d_in[3];  bn  = (const float*)d_in[4];
        We  = (const float*)d_in[5];  be  = (const float*)d_in[6];
        l1g = (const float*)d_in[7];  l1b = (const float*)d_in[8];
        Wq  = (const float*)d_in[9];  Wk  = (const float*)d_in[10];
        Wv  = (const float*)d_in[11]; Wo  = (const float*)d_in[12];
        bo  = (const float*)d_in[13]; l2g = (const float*)d_in[14];
        l2b = (const float*)d_in[15]; W1  = (const float*)d_in[16];
        b1  = (const float*)d_in[17]; W2  = (const float*)d_in[18];
        b2  = (const float*)d_in[19]; mask = d_in[20];
    }

    float *p_emb, *p_cvec, *p_qkv;
    __nv_bfloat16 *p_x0h, *p_x0l, *p_hh, *p_hl, *p_mhah, *p_mhal, *p_ffh, *p_ffl;
    __nv_bfloat16 *p_WnImg, *p_WprojImg, *p_WbigImg, *p_W1Img, *p_W2Img;
    cudaGetSymbolAddress((void**)&p_emb,   g_emb);
    cudaGetSymbolAddress((void**)&p_cvec,  g_cvec);
    cudaGetSymbolAddress((void**)&p_x0h,   g_x0h);
    cudaGetSymbolAddress((void**)&p_x0l,   g_x0l);
    cudaGetSymbolAddress((void**)&p_hh,    g_hh);
    cudaGetSymbolAddress((void**)&p_hl,    g_hl);
    cudaGetSymbolAddress((void**)&p_mhah,  g_mhah);
    cudaGetSymbolAddress((void**)&p_mhal,  g_mhal);
    cudaGetSymbolAddress((void**)&p_ffh,   g_ffh);
    cudaGetSymbolAddress((void**)&p_ffl,   g_ffl);
    cudaGetSymbolAddress((void**)&p_qkv,   g_qkv);
    cudaGetSymbolAddress((void**)&p_WnImg,   g_WnImg);
    cudaGetSymbolAddress((void**)&p_WprojImg, g_WprojImg);
    cudaGetSymbolAddress((void**)&p_WbigImg,  g_WbigImg);
    cudaGetSymbolAddress((void**)&p_W1Img,    g_W1Img);
    cudaGetSymbolAddress((void**)&p_W2Img,    g_W2Img);

    const int ATTN_SMEM = ATTN_SMEM_FLOATS * 4;
    cudaFuncSetAttribute(attn_kernel, cudaFuncAttributeMaxDynamicSharedMemorySize, ATTN_SMEM);

    float* out = (float*)d_out;
    size_t need_attn = (size_t)BB * DD + (size_t)LLAYERS * NHH * BB * NNODE * NNODE;
    int write_attn = ((size_t)out_size >= need_attn) ? 1 : 0;
    float* attn_base = out + BB * DD;

    fused_prep<<<PREP_BLOCKS, 256>>>(Wn, Wq, Wk, Wv, We, Wo, W1, W2, be, bo);
    detect_mask_kernel<<<1, 256>>>((const unsigned char*)mask);
    concat_kernel<<<(ROWS * 64 + 255) / 256, 256>>>(nf, st);
    // 4th launch: Wn GEMM (stays in the ncu capture slot for A/B comparison)
    mm_mma<<<dim3(2, 64), 256>>>(p_x0h, p_x0l, p_WnImg, 128, 256,
        bn, nullptr, 0, p_emb, 128, nullptr, nullptr, 0, 0);

    for (int l = 0; l < LLAYERS; l++) {
        const float* be_l = be + (size_t)l * 128;
        ln_kernel<<<512, 256>>>(p_emb, l1g + l * 128, l1b + l * 128, 1e-5f);
        mm_mma<<<dim3(16, 64), 256>>>(p_hh, p_hl,
            p_WprojImg + (size_t)l * 2 * 128 * 1024, 1024, 128,
            nullptr, nullptr, 0, p_qkv, 1024, nullptr, nullptr, 0, 0);

        attn_kernel<<<dim3(32, 64), 256, ATTN_SMEM>>>(ef, mask, be_l,
                                                      attn_base, write_attn, l);

        mm_mma<<<dim3(2, 64), 256>>>(p_mhah, p_mhal,
            p_WbigImg + (size_t)l * 2 * 512 * 128, 128, 512,
            p_cvec + l * 128, p_emb, 128, p_emb, 128, nullptr, nullptr, 0, 0);

        ln_kernel<<<512, 256>>>(p_emb, l2g + l * 128, l2b + l * 128, 1e-6f);
        mm_mma<<<dim3(8, 64), 256>>>(p_hh, p_hl,
            p_W1Img + (size_t)l * 2 * 128 * 512, 512, 128,
            b1 + (size_t)l * 512, nullptr, 0, nullptr, 0, p_ffh, p_ffl, 512, 1);
        mm_mma<<<dim3(2, 64), 256>>>(p_ffh, p_ffl,
            p_W2Img + (size_t)l * 2 * 512 * 128, 128, 512,
            b2 + (size_t)l * 128, p_emb, 128, p_emb, 128, nullptr, nullptr, 0, 0);
    }

    mean_kernel<<<BB, 128>>>(out);
}

// round 12
// speedup vs baseline: 1.0820x; 1.0301x over previous
#include <cuda_runtime.h>
#include <cuda_bf16.h>
#include <math.h>
#include <stdint.h>

// Problem dims
#define BB 64
#define NNODE 64
#define DD 128
#define NHH 2
#define LLAYERS 2
#define ROWS (BB*NNODE)          // 4096

// ============================================================================
// Helpers
// ============================================================================
__device__ __forceinline__ uint32_t smem_u32(const void* p) {
    uint32_t a;
    asm("{ .reg .u64 t; cvta.to.shared.u64 t, %1; cvt.u32.u64 %0, t; }"
        : "=r"(a) : "l"(p));
    return a;
}

__device__ __forceinline__ void ldmA(uint32_t* a, uint32_t addr) {
    asm volatile("ldmatrix.sync.aligned.m8n8.x4.shared.b16 {%0,%1,%2,%3}, [%4];"
        : "=r"(a[0]), "=r"(a[1]), "=r"(a[2]), "=r"(a[3]) : "r"(addr));
}
__device__ __forceinline__ void ldmBt(uint32_t* b, uint32_t addr) {
    asm volatile("ldmatrix.sync.aligned.m8n8.x2.trans.shared.b16 {%0,%1}, [%2];"
        : "=r"(b[0]), "=r"(b[1]) : "r"(addr));
}
__device__ __forceinline__ void mma16816(float* d, const uint32_t* a, const uint32_t* b) {
    asm volatile("mma.sync.aligned.m16n8k16.row.col.f32.bf16.bf16.f32 "
        "{%0,%1,%2,%3}, {%4,%5,%6,%7}, {%8,%9}, {%0,%1,%2,%3};"
        : "+f"(d[0]), "+f"(d[1]), "+f"(d[2]), "+f"(d[3])
        : "r"(a[0]), "r"(a[1]), "r"(a[2]), "r"(a[3]), "r"(b[0]), "r"(b[1]));
}
__device__ __forceinline__ void cp16(uint32_t saddr, const void* gptr) {
    asm volatile("cp.async.cg.shared.global [%0], [%1], 16;"
        :: "r"(saddr), "l"(gptr));
}
#define CP_COMMIT() asm volatile("cp.async.commit_group;" ::: "memory")
template <int N>
__device__ __forceinline__ void cp_wait() {
    asm volatile("cp.async.wait_group %0;" :: "n"(N) : "memory");
}

__device__ __forceinline__ void bf16split(float v, __nv_bfloat16* hi, __nv_bfloat16* lo) {
    __nv_bfloat16 h = __float2bfloat16(v);
    *hi = h;
    *lo = __float2bfloat16(v - __bfloat162float(h));
}

// ============================================================================
// Scratch (device globals; no allocation)
// ============================================================================
__device__ __nv_bfloat16 g_x0h [ROWS*256];
__device__ __nv_bfloat16 g_x0l [ROWS*256];
__device__ float         g_emb [ROWS*128];
__device__ __nv_bfloat16 g_hh  [ROWS*128];
__device__ __nv_bfloat16 g_hl  [ROWS*128];
__device__ float         g_qkv [ROWS*1024];
__device__ __nv_bfloat16 g_mhah[ROWS*512];
__device__ __nv_bfloat16 g_mhal[ROWS*512];
__device__ __nv_bfloat16 g_ffh [ROWS*512];
__device__ __nv_bfloat16 g_ffl [ROWS*512];
__device__ float         g_cvec[LLAYERS*128];
__device__ float         g_part[4*ROWS*128];    // split-K partials (8 MB)
__device__ int           g_mask_mode;

// Weight images, natural [K][N] bf16, hi plane then lo plane
__device__ __nv_bfloat16 g_WnImg  [2*256*128];
__device__ __nv_bfloat16 g_WprojImg[LLAYERS][2*128*1024];
__device__ __nv_bfloat16 g_WbigImg [LLAYERS][2*512*128];
__device__ __nv_bfloat16 g_W1Img   [LLAYERS][2*128*512];
__device__ __nv_bfloat16 g_W2Img   [LLAYERS][2*512*128];

// ============================================================================
// mask dtype detection (parallel)
// ============================================================================
__global__ void detect_mask_kernel(const unsigned char* __restrict__ m)
{
    __shared__ int cnt[2];
    if (threadIdx.x < 2) cnt[threadIdx.x] = 0;
    __syncthreads();
    int u8 = 0, f32 = 0;
    for (int i = threadIdx.x; i < 4096; i += 256) {
        unsigned char v = m[i];
        if (v) {
            int r = i & 3;
            if (r == 1) u8++;
            else if (r == 3) f32++;
        }
    }
    if (u8)  atomicAdd(&cnt[0], u8);
    if (f32) atomicAdd(&cnt[1], f32);
    __syncthreads();
    if (threadIdx.x == 0)
        g_mask_mode = cnt[0] ? 0 : (cnt[1] ? 2 : 1);
}
__device__ __forceinline__ bool mask_at(const void* mp, size_t idx, int mode)
{
    if (mode == 0) return ((const unsigned char*)mp)[idx] != 0;
    if (mode == 1) return ((const int*)mp)[idx] != 0;
    return ((const float*)mp)[idx] != 0.0f;
}

// ============================================================================
// Fused prologue: ALL weight-image prep in one kernel (blockIdx dispatch)
// ============================================================================
#define PREP_BLOCKS (128 + 768 + 256 + 256 + 256 + 512 + 512 + 1)
__global__ void fused_prep(const float* __restrict__ Wn, const float* __restrict__ Wq,
                           const float* __restrict__ Wk, const float* __restrict__ Wv,
                           const float* __restrict__ We, const float* __restrict__ Wo,
                           const float* __restrict__ W1, const float* __restrict__ W2,
                           const float* __restrict__ be, const float* __restrict__ bo)
{
    int blk = blockIdx.x, tid = threadIdx.x;
    __nv_bfloat16 hi, lo;

    if (blk < 128) {
        int t = blk * 256 + tid;
        bf16split(Wn[t], &hi, &lo);
        g_WnImg[t] = hi; g_WnImg[32768 + t] = lo;
        return;
    }
    blk -= 128;
    if (blk < 768) {
        int idx = blk * 256 + tid;
        int l = idx / 98304, r = idx % 98304;
        int k = r / 768, n = r % 768;
        const float* W = (n < 256) ? Wq : (n < 512 ? Wk : Wv);
        float v = W[(size_t)l * 32768 + (size_t)k * 256 + (n & 255)];
        bf16split(v, &hi, &lo);
        g_WprojImg[l][(size_t)k * 1024 + n]          = hi;
        g_WprojImg[l][131072 + (size_t)k * 1024 + n] = lo;
        return;
    }
    blk -= 768;
    if (blk < 256) {
        int idx = blk * 256 + tid;
        int l = idx >> 15, r = idx & 32767;
        int h = r >> 14, r2 = r & 16383;
        int e = r2 >> 7, d = r2 & 127;
        const float* wq = Wq + (size_t)l * 32768 + (size_t)d * 256 + h * 128;
        const float* we = We + (size_t)l * 16384 + (size_t)e * 128;
        float acc = 0.0f;
        #pragma unroll 8
        for (int c = 0; c < 128; c++) acc += wq[c] * we[c];
        size_t o = (size_t)d * 1024 + 768 + h * 128 + e;
        bf16split(acc, &hi, &lo);
        g_WprojImg[l][o] = hi; g_WprojImg[l][131072 + o] = lo;
        return;
    }
    blk -= 256;
    if (blk < 256) {
        int idx = blk * 256 + tid;
        int l = idx >> 15, t2 = idx & 32767;
        bf16split(Wo[(size_t)l * 32768 + t2], &hi, &lo);
        g_WbigImg[l][t2] = hi; g_WbigImg[l][65536 + t2] = lo;
        return;
    }
    blk -= 256;
    if (blk < 256) {
        int idx = blk * 256 + tid;
        int l = idx >> 15, r = idx & 32767;
        int h = r >> 14, r2 = r & 16383;
        int f = r2 >> 7, n = r2 & 127;
        const float* we = We + (size_t)l * 16384 + (size_t)f * 128;
        const float* wo = Wo + (size_t)l * 32768 + (size_t)(h * 128) * 128 + n;
        float acc = 0.0f;
        #pragma unroll 8
        for (int e = 0; e < 128; e++) acc += we[e] * wo[(size_t)e * 128];
        size_t o = (size_t)(256 + h * 128 + f) * 128 + n;
        bf16split(acc, &hi, &lo);
        g_WbigImg[l][o] = hi; g_WbigImg[l][65536 + o] = lo;
        return;
    }
    blk -= 256;
    if (blk < 512) {
        int idx = blk * 256 + tid;
        int l = idx >> 16, t2 = idx & 65535;
        bf16split(W1[(size_t)l * 65536 + t2], &hi, &lo);
        g_W1Img[l][t2] = hi; g_W1Img[l][65536 + t2] = lo;
        return;
    }
    blk -= 512;
    if (blk < 512) {
        int idx = blk * 256 + tid;
        int l = idx >> 16, t2 = idx & 65535;
        bf16split(W2[(size_t)l * 65536 + t2], &hi, &lo);
        g_W2Img[l][t2] = hi; g_W2Img[l][65536 + t2] = lo;
        return;
    }
    blk -= 512;
    {
        int l = tid >> 7, d = tid & 127;
        float acc = bo[l * 128 + d];
        const float* wo = Wo + (size_t)l * 32768;
        const float* bel = be + l * 128;
        for (int r = 0; r < 256; r++) acc += bel[r & 127] * wo[(size_t)r * 128 + d];
        g_cvec[l * 128 + d] = acc;
    }
}

// ============================================================================
// concat(node_feat, stpe) -> bf16 pairs [4096,256]
// ============================================================================
__global__ void concat_kernel(const float* __restrict__ nf, const float* __restrict__ st)
{
    int t = blockIdx.x * blockDim.x + threadIdx.x;
    if (t < ROWS * 64) {
        int row = t >> 6, c4 = t & 63;
        float4 val = (c4 < 32) ? ((const float4*)nf)[row * 32 + c4]
                               : ((const float4*)st)[row * 32 + (c4 - 32)];
        size_t o = (size_t)row * 256 + c4 * 4;
        float vv[4] = {val.x, val.y, val.z, val.w};
        #pragma unroll
        for (int j = 0; j < 4; j++) {
            __nv_bfloat16 hi, lo; bf16split(vv[j], &hi, &lo);
            g_x0h[o + j] = hi; g_x0l[o + j] = lo;
        }
    }
}

// ============================================================================
// LayerNorm -> bf16 pairs
// ============================================================================
__global__ void ln_kernel(const float* __restrict__ x,
                          const float* __restrict__ g, const float* __restrict__ b,
                          float eps)
{
    int row  = blockIdx.x * 8 + (threadIdx.x >> 5);
    int lane = threadIdx.x & 31;
    const float* xr = x + (size_t)row * 128;
    float v0 = xr[lane], v1 = xr[lane + 32], v2 = xr[lane + 64], v3 = xr[lane + 96];
    float s = v0 + v1 + v2 + v3;
    #pragma unroll
    for (int o = 16; o; o >>= 1) s += __shfl_xor_sync(0xffffffffu, s, o);
    float mu = s * (1.0f / 128.0f);
    float d0 = v0 - mu, d1 = v1 - mu, d2 = v2 - mu, d3 = v3 - mu;
    float q = d0*d0 + d1*d1 + d2*d2 + d3*d3;
    #pragma unroll
    for (int o = 16; o; o >>= 1) q += __shfl_xor_sync(0xffffffffu, q, o);
    float inv = rsqrtf(q * (1.0f / 128.0f) + eps);
    size_t base = (size_t)row * 128;
    float y0 = d0 * inv * g[lane]      + b[lane];
    float y1 = d1 * inv * g[lane + 32] + b[lane + 32];
    float y2 = d2 * inv * g[lane + 64] + b[lane + 64];
    float y3 = d3 * inv * g[lane + 96] + b[lane + 96];
    __nv_bfloat16 hi, lo;
    bf16split(y0, &hi, &lo); g_hh[base + lane]      = hi; g_hl[base + lane]      = lo;
    bf16split(y1, &hi, &lo); g_hh[base + lane + 32] = hi; g_hl[base + lane + 32] = lo;
    bf16split(y2, &hi, &lo); g_hh[base + lane + 64] = hi; g_hl[base + lane + 64] = lo;
    bf16split(y3, &hi, &lo); g_hh[base + lane + 96] = hi; g_hl[base + lane + 96] = lo;
}

// ============================================================================
// mma.sync GEMM with cp.async double-buffering (R9 config: 128 thr, 4 warps).
// 64x64 tile, warp tile 32x32, K-chunk 32.
// ============================================================================
#define AKP 40
#define BNP 72
__global__ __launch_bounds__(128) void mm_mma(
    const __nv_bfloat16* __restrict__ Ah, const __nv_bfloat16* __restrict__ Al,
    const __nv_bfloat16* __restrict__ Wimg, int N, int K,
    const float* __restrict__ bias,
    const float* __restrict__ res, int ldr,
    float* __restrict__ outf, int ldo,
    __nv_bfloat16* __restrict__ oh, __nv_bfloat16* __restrict__ ol, int ldp,
    int relu)
{
    __shared__ __nv_bfloat16 sA[2][2][64 * AKP];   // [stage][hi/lo]
    __shared__ __nv_bfloat16 sB[2][2][32 * BNP];

    int tid = threadIdx.x, lane = tid & 31, wid = tid >> 5;
    int m0 = blockIdx.y * 64, n0 = blockIdx.x * 64;
    int wm = (wid >> 1) * 32, wn = (wid & 1) * 32;

    const __nv_bfloat16* Wh = Wimg;
    const __nv_bfloat16* Wl = Wimg + (size_t)N * K;

    float acc[2][4][4];
    #pragma unroll
    for (int mt = 0; mt < 2; mt++)
        #pragma unroll
        for (int nt = 0; nt < 4; nt++)
            #pragma unroll
            for (int c = 0; c < 4; c++) acc[mt][nt][c] = 0.0f;

    uint32_t sA_b[2][2], sB_b[2][2];
    #pragma unroll
    for (int s = 0; s < 2; s++)
        #pragma unroll
        for (int p = 0; p < 2; p++) {
            sA_b[s][p] = smem_u32(sA[s][p]);
            sB_b[s][p] = smem_u32(sB[s][p]);
        }

    int ar0 = tid >> 2, ac0 = (tid & 3) * 8;
    int br0 = tid >> 3, bc0 = (tid & 7) * 8;

    int la_row = lane & 15, la_col = (lane >> 4) * 8;
    int lb_row = lane & 15;

    int nch = K >> 5;

    {
        #pragma unroll
        for (int i = 0; i < 2; i++) {
            int ar = ar0 + i * 32;
            cp16(sA_b[0][0] + (uint32_t)(ar * AKP + ac0) * 2,
                 Ah + (size_t)(m0 + ar) * K + ac0);
            cp16(sA_b[0][1] + (uint32_t)(ar * AKP + ac0) * 2,
                 Al + (size_t)(m0 + ar) * K + ac0);
            int br = br0 + i * 16;
            cp16(sB_b[0][0] + (uint32_t)(br * BNP + bc0) * 2,
                 Wh + (size_t)br * N + n0 + bc0);
            cp16(sB_b[0][1] + (uint32_t)(br * BNP + bc0) * 2,
                 Wl + (size_t)br * N + n0 + bc0);
        }
        CP_COMMIT();
    }

    for (int ch = 0; ch < nch; ch++) {
        int st = ch & 1;
        bool more = (ch + 1 < nch);
        if (more) {
            int k0 = (ch + 1) << 5;
            int s2 = st ^ 1;
            #pragma unroll
            for (int i = 0; i < 2; i++) {
                int ar = ar0 + i * 32;
                cp16(sA_b[s2][0] + (uint32_t)(ar * AKP + ac0) * 2,
                     Ah + (size_t)(m0 + ar) * K + k0 + ac0);
                cp16(sA_b[s2][1] + (uint32_t)(ar * AKP + ac0) * 2,
                     Al + (size_t)(m0 + ar) * K + k0 + ac0);
                int br = br0 + i * 16;
                cp16(sB_b[s2][0] + (uint32_t)(br * BNP + bc0) * 2,
                     Wh + (size_t)(k0 + br) * N + n0 + bc0);
                cp16(sB_b[s2][1] + (uint32_t)(br * BNP + bc0) * 2,
                     Wl + (size_t)(k0 + br) * N + n0 + bc0);
            }
            CP_COMMIT();
            cp_wait<1>();
        } else {
            cp_wait<0>();
        }
        __syncthreads();

        #pragma unroll
        for (int ks = 0; ks < 2; ks++) {
            int kb = ks * 16;
            uint32_t bH[4][2], bL[4][2];
            #pragma unroll
            for (int nt = 0; nt < 4; nt++) {
                uint32_t boff = (uint32_t)((kb + lb_row) * BNP + wn + nt * 8) * 2;
                ldmBt(bH[nt], sB_b[st][0] + boff);
                ldmBt(bL[nt], sB_b[st][1] + boff);
            }
            #pragma unroll
            for (int mt = 0; mt < 2; mt++) {
                uint32_t aoff = (uint32_t)((wm + mt * 16 + la_row) * AKP + kb + la_col) * 2;
                uint32_t aH[4], aL[4];
                ldmA(aH, sA_b[st][0] + aoff);
                ldmA(aL, sA_b[st][1] + aoff);
                #pragma unroll
                for (int nt = 0; nt < 4; nt++) {
                    mma16816(acc[mt][nt], aH, bH[nt]);
                    mma16816(acc[mt][nt], aH, bL[nt]);
                    mma16816(acc[mt][nt], aL, bH[nt]);
                }
            }
        }
        __syncthreads();
    }

    int g = lane >> 2, tg = lane & 3;
    #pragma unroll
    for (int mt = 0; mt < 2; mt++) {
        #pragma unroll
        for (int nt = 0; nt < 4; nt++) {
            int col = n0 + wn + nt * 8 + tg * 2;
            #pragma unroll
            for (int half = 0; half < 2; half++) {
                int row = m0 + wm + mt * 16 + g + half * 8;
                float v0 = acc[mt][nt][half * 2];
                float v1 = acc[mt][nt][half * 2 + 1];
                if (bias) { v0 += bias[col]; v1 += bias[col + 1]; }
                if (res) {
                    v0 += res[(size_t)row * ldr + col];
                    v1 += res[(size_t)row * ldr + col + 1];
                }
                if (relu) { v0 = fmaxf(v0, 0.0f); v1 = fmaxf(v1, 0.0f); }
                if (outf) {
                    outf[(size_t)row * ldo + col]     = v0;
                    outf[(size_t)row * ldo + col + 1] = v1;
                }
                if (oh) {
                    __nv_bfloat16 hi, lo;
                    bf16split(v0, &hi, &lo);
                    oh[(size_t)row * ldp + col] = hi;
                    ol[(size_t)row * ldp + col] = lo;
                    bf16split(v1, &hi, &lo);
                    oh[(size_t)row * ldp + col + 1] = hi;
                    ol[(size_t)row * ldp + col + 1] = lo;
                }
            }
        }
    }
}

// ============================================================================
// Split-K GEMM: K=512 split into 4 slices of 128 via blockIdx.z.
// Writes fp32 partials to g_part[z]. N must be 128. Grid (2, 64, 4).
// ============================================================================
__global__ __launch_bounds__(128) void mm_split(
    const __nv_bfloat16* __restrict__ Ah, const __nv_bfloat16* __restrict__ Al,
    const __nv_bfloat16* __restrict__ Wimg, int N, int K)
{
    __shared__ __nv_bfloat16 sA[2][2][64 * AKP];
    __shared__ __nv_bfloat16 sB[2][2][32 * BNP];

    int tid = threadIdx.x, lane = tid & 31, wid = tid >> 5;
    int m0 = blockIdx.y * 64, n0 = blockIdx.x * 64;
    int z = blockIdx.z;
    int kbase = z << 7;                    // 128 per slice
    int wm = (wid >> 1) * 32, wn = (wid & 1) * 32;

    const __nv_bfloat16* Wh = Wimg;
    const __nv_bfloat16* Wl = Wimg + (size_t)N * K;

    float acc[2][4][4];
    #pragma unroll
    for (int mt = 0; mt < 2; mt++)
        #pragma unroll
        for (int nt = 0; nt < 4; nt++)
            #pragma unroll
            for (int c = 0; c < 4; c++) acc[mt][nt][c] = 0.0f;

    uint32_t sA_b[2][2], sB_b[2][2];
    #pragma unroll
    for (int s = 0; s < 2; s++)
        #pragma unroll
        for (int p = 0; p < 2; p++) {
            sA_b[s][p] = smem_u32(sA[s][p]);
            sB_b[s][p] = smem_u32(sB[s][p]);
        }

    int ar0 = tid >> 2, ac0 = (tid & 3) * 8;
    int br0 = tid >> 3, bc0 = (tid & 7) * 8;
    int la_row = lane & 15, la_col = (lane >> 4) * 8;
    int lb_row = lane & 15;

    {
        #pragma unroll
        for (int i = 0; i < 2; i++) {
            int ar = ar0 + i * 32;
            cp16(sA_b[0][0] + (uint32_t)(ar * AKP + ac0) * 2,
                 Ah + (size_t)(m0 + ar) * K + kbase + ac0);
            cp16(sA_b[0][1] + (uint32_t)(ar * AKP + ac0) * 2,
                 Al + (size_t)(m0 + ar) * K + kbase + ac0);
            int br = br0 + i * 16;
            cp16(sB_b[0][0] + (uint32_t)(br * BNP + bc0) * 2,
                 Wh + (size_t)(kbase + br) * N + n0 + bc0);
            cp16(sB_b[0][1] + (uint32_t)(br * BNP + bc0) * 2,
                 Wl + (size_t)(kbase + br) * N + n0 + bc0);
        }
        CP_COMMIT();
    }

    for (int ch = 0; ch < 4; ch++) {
        int st = ch & 1;
        bool more = (ch + 1 < 4);
        if (more) {
            int k0 = kbase + ((ch + 1) << 5);
            int s2 = st ^ 1;
            #pragma unroll
            for (int i = 0; i < 2; i++) {
                int ar = ar0 + i * 32;
                cp16(sA_b[s2][0] + (uint32_t)(ar * AKP + ac0) * 2,
                     Ah + (size_t)(m0 + ar) * K + k0 + ac0);
                cp16(sA_b[s2][1] + (uint32_t)(ar * AKP + ac0) * 2,
                     Al + (size_t)(m0 + ar) * K + k0 + ac0);
                int br = br0 + i * 16;
                cp16(sB_b[s2][0] + (uint32_t)(br * BNP + bc0) * 2,
                     Wh + (size_t)(k0 + br) * N + n0 + bc0);
                cp16(sB_b[s2][1] + (uint32_t)(br * BNP + bc0) * 2,
                     Wl + (size_t)(k0 + br) * N + n0 + bc0);
            }
            CP_COMMIT();
            cp_wait<1>();
        } else {
            cp_wait<0>();
        }
        __syncthreads();

        #pragma unroll
        for (int ks = 0; ks < 2; ks++) {
            int kb = ks * 16;
            uint32_t bH[4][2], bL[4][2];
            #pragma unroll
            for (int nt = 0; nt < 4; nt++) {
                uint32_t boff = (uint32_t)((kb + lb_row) * BNP + wn + nt * 8) * 2;
                ldmBt(bH[nt], sB_b[st][0] + boff);
                ldmBt(bL[nt], sB_b[st][1] + boff);
            }
            #pragma unroll
            for (int mt = 0; mt < 2; mt++) {
                uint32_t aoff = (uint32_t)((wm + mt * 16 + la_row) * AKP + kb + la_col) * 2;
                uint32_t aH[4], aL[4];
                ldmA(aH, sA_b[st][0] + aoff);
                ldmA(aL, sA_b[st][1] + aoff);
                #pragma unroll
                for (int nt = 0; nt < 4; nt++) {
                    mma16816(acc[mt][nt], aH, bH[nt]);
                    mma16816(acc[mt][nt], aH, bL[nt]);
                    mma16816(acc[mt][nt], aL, bH[nt]);
                }
            }
        }
        __syncthreads();
    }

    float* part = g_part + (size_t)z * ROWS * 128;
    int g = lane >> 2, tg = lane & 3;
    #pragma unroll
    for (int mt = 0; mt < 2; mt++) {
        #pragma unroll
        for (int nt = 0; nt < 4; nt++) {
            int col = n0 + wn + nt * 8 + tg * 2;
            #pragma unroll
            for (int half = 0; half < 2; half++) {
                int row = m0 + wm + mt * 16 + g + half * 8;
                part[(size_t)row * 128 + col]     = acc[mt][nt][half * 2];
                part[(size_t)row * 128 + col + 1] = acc[mt][nt][half * 2 + 1];
            }
        }
    }
}

// reduce 4 split-K partials + bias + residual(inout) -> inout (fp32)
__global__ void split_reduce(const float* __restrict__ bias,
                             float* __restrict__ inout)
{
    int o = blockIdx.x * 256 + threadIdx.x;   // 524288 outputs
    float s = g_part[o] + g_part[o + ROWS*128] + g_part[o + 2*ROWS*128]
            + g_part[o + 3*ROWS*128];
    inout[o] = s + bias[o & 127] + inout[o];
}

// ============================================================================
// fused attention v3 — 2 query rows per CTA, partial-sum buffer (R9 version)
// ============================================================================
#define ATTN_SMEM_FLOATS (16384 + 8192 + 512 + 512 + 256 + 256 + 128)
__global__ __launch_bounds__(256) void attn_kernel(
    const float* __restrict__ edge,
    const void* __restrict__ mask,
    const float* __restrict__ be_l,
    float* __restrict__ attn_out, int write_attn,
    int layer)
{
    extern __shared__ float sm[];
    float* s_e    = sm;
    float* s_part = s_e + 16384;
    float* s_q    = s_part + 8192;
    float* s_qe   = s_q + 512;
    float* s_sc   = s_qe + 512;
    float* s_att  = s_sc + 256;
    float* s_be   = s_att + 256;

    int b = blockIdx.y, i0 = blockIdx.x * 2;
    int t = threadIdx.x, lane = t & 31, w = t >> 5;
    int mode = g_mask_mode;
    size_t qrow0 = (size_t)(b * 64 + i0) * 1024;

    const float4* esrc = (const float4*)(edge + ((size_t)(b * 64 + i0)) * 8192);
    #pragma unroll
    for (int r = 0; r < 16; r++)
        ((float4*)s_e)[t + r * 256] = esrc[t + r * 256];
    s_q [t]       = g_qkv[qrow0 + t];
    s_q [256 + t] = g_qkv[qrow0 + 1024 + t];
    s_qe[t]       = g_qkv[qrow0 + 768 + t];
    s_qe[256 + t] = g_qkv[qrow0 + 1024 + 768 + t];
    if (t < 128) s_be[t] = be_l[t];
    __syncthreads();

    {
        int h = w >> 2;
        float4 q0  = *(float4*)&s_q [h * 128 + lane * 4];
        float4 q1  = *(float4*)&s_q [256 + h * 128 + lane * 4];
        float4 qe0 = *(float4*)&s_qe[h * 128 + lane * 4];
        float4 qe1 = *(float4*)&s_qe[256 + h * 128 + lane * 4];
        float4 be4 = *(float4*)&s_be[lane * 4];
        float qb0 = q0.x*be4.x + q0.y*be4.y + q0.z*be4.z + q0.w*be4.w;
        float qb1 = q1.x*be4.x + q1.y*be4.y + q1.z*be4.z + q1.w*be4.w;
        #pragma unroll
        for (int off = 16; off; off >>= 1) {
            qb0 += __shfl_xor_sync(0xffffffffu, qb0, off);
            qb1 += __shfl_xor_sync(0xffffffffu, qb1, off);
        }

        #pragma unroll
        for (int oo = 0; oo < 16; oo++) {
            int j = (w & 3) * 16 + oo;
            float4 k4 = *(const float4*)(g_qkv + (size_t)(b * 64 + j) * 1024
                                         + 256 + h * 128 + lane * 4);
            float4 e0 = *(float4*)&s_e[j * 128 + lane * 4];
            float4 e1 = *(float4*)&s_e[8192 + j * 128 + lane * 4];
            float d0 = q0.x*k4.x + q0.y*k4.y + q0.z*k4.z + q0.w*k4.w
                     + qe0.x*e0.x + qe0.y*e0.y + qe0.z*e0.z + qe0.w*e0.w;
            float d1 = q1.x*k4.x + q1.y*k4.y + q1.z*k4.z + q1.w*k4.w
                     + qe1.x*e1.x + qe1.y*e1.y + qe1.z*e1.z + qe1.w*e1.w;
            #pragma unroll
            for (int off = 16; off; off >>= 1) {
                d0 += __shfl_xor_sync(0xffffffffu, d0, off);
                d1 += __shfl_xor_sync(0xffffffffu, d1, off);
            }
            if (lane == 0) {
                s_sc[h * 64 + j]       = d0 + qb0;
                s_sc[128 + h * 64 + j] = d1 + qb1;
            }
        }
    }
    __syncthreads();

    if (w < 4) {
        const float invT = 0.08838834764831843f;
        int ii = w >> 1, h = w & 1;
        int iabs = i0 + ii;
        size_t mbase = ((size_t)(b * 64 + iabs)) * 64;
        float v0 = s_sc[ii * 128 + h * 64 + lane]      * invT;
        float v1 = s_sc[ii * 128 + h * 64 + lane + 32] * invT;
        if (mask_at(mask, mbase + lane,      mode)) v0 = 1e-10f;
        if (mask_at(mask, mbase + lane + 32, mode)) v1 = 1e-10f;
        float mx = fmaxf(v0, v1);
        #pragma unroll
        for (int off = 16; off; off >>= 1)
            mx = fmaxf(mx, __shfl_xor_sync(0xffffffffu, mx, off));
        float e0 = expf(v0 - mx), e1 = expf(v1 - mx);
        float s = e0 + e1;
        #pragma unroll
        for (int off = 16; off; off >>= 1)
            s += __shfl_xor_sync(0xffffffffu, s, off);
        float inv = 1.0f / s;
        e0 *= inv; e1 *= inv;
        s_att[ii * 128 + h * 64 + lane]      = e0;
        s_att[ii * 128 + h * 64 + lane + 32] = e1;
        if (write_attn) {
            float* ap = attn_out +
                ((((size_t)layer * NHH + h) * BB + b) * NNODE + iabs) * NNODE;
            ap[lane]      = e0;
            ap[lane + 32] = e1;
        }
    }
    __syncthreads();

    {
        float a0h0[4] = {}, a0h1[4] = {}, a0e0[4] = {}, a0e1[4] = {};
        float a1h0[4] = {}, a1h1[4] = {}, a1e0[4] = {}, a1e1[4] = {};
        #pragma unroll
        for (int jj = 0; jj < 8; jj++) {
            int j = w + jj * 8;
            const float* vrow = g_qkv + (size_t)(b * 64 + j) * 1024 + 512;
            float4 v0 = *(const float4*)(vrow + lane * 4);
            float4 v1 = *(const float4*)(vrow + 128 + lane * 4);
            float4 e0 = *(float4*)&s_e[j * 128 + lane * 4];
            float4 e1 = *(float4*)&s_e[8192 + j * 128 + lane * 4];
            float w00 = s_att[j],       w01 = s_att[64 + j];
            float w10 = s_att[128 + j], w11 = s_att[192 + j];
            a0h0[0] += w00*v0.x; a0h0[1] += w00*v0.y; a0h0[2] += w00*v0.z; a0h0[3] += w00*v0.w;
            a0h1[0] += w01*v1.x; a0h1[1] += w01*v1.y; a0h1[2] += w01*v1.z; a0h1[3] += w01*v1.w;
            a0e0[0] += w00*e0.x; a0e0[1] += w00*e0.y; a0e0[2] += w00*e0.z; a0e0[3] += w00*e0.w;
            a0e1[0] += w01*e0.x; a0e1[1] += w01*e0.y; a0e1[2] += w01*e0.z; a0e1[3] += w01*e0.w;
            a1h0[0] += w10*v0.x; a1h0[1] += w10*v0.y; a1h0[2] += w10*v0.z; a1h0[3] += w10*v0.w;
            a1h1[0] += w11*v1.x; a1h1[1] += w11*v1.y; a1h1[2] += w11*v1.z; a1h1[3] += w11*v1.w;
            a1e0[0] += w10*e1.x; a1e0[1] += w10*e1.y; a1e0[2] += w10*e1.z; a1e0[3] += w10*e1.w;
            a1e1[0] += w11*e1.x; a1e1[1] += w11*e1.y; a1e1[2] += w11*e1.z; a1e1[3] += w11*e1.w;
        }
        float* pw = s_part + w * 1024;
        *(float4*)&pw[lane * 4]       = make_float4(a0h0[0], a0h0[1], a0h0[2], a0h0[3]);
        *(float4*)&pw[128 + lane * 4] = make_float4(a0h1[0], a0h1[1], a0h1[2], a0h1[3]);
        *(float4*)&pw[256 + lane * 4] = make_float4(a0e0[0], a0e0[1], a0e0[2], a0e0[3]);
        *(float4*)&pw[384 + lane * 4] = make_float4(a0e1[0], a0e1[1], a0e1[2], a0e1[3]);
        *(float4*)&pw[512 + lane * 4] = make_float4(a1h0[0], a1h0[1], a1h0[2], a1h0[3]);
        *(float4*)&pw[640 + lane * 4] = make_float4(a1h1[0], a1h1[1], a1h1[2], a1h1[3]);
        *(float4*)&pw[768 + lane * 4] = make_float4(a1e0[0], a1e0[1], a1e0[2], a1e0[3]);
        *(float4*)&pw[896 + lane * 4] = make_float4(a1e1[0], a1e1[1], a1e1[2], a1e1[3]);
    }
    __syncthreads();

    #pragma unroll
    for (int rep = 0; rep < 4; rep++) {
        int o = t + rep * 256;
        float s = 0.0f;
        #pragma unroll
        for (int ww = 0; ww < 8; ww++) s += s_part[ww * 1024 + o];
        int ii = o >> 9, seg = o & 511;
        size_t mo = ((size_t)(b * 64 + i0 + ii)) * 512 + seg;
        __nv_bfloat16 hi, lo; bf16split(s, &hi, &lo);
        g_mhah[mo] = hi; g_mhal[mo] = lo;
    }
}

// ---------------- final mean over nodes ----------------
__global__ void mean_kernel(float* __restrict__ out)
{
    int b = blockIdx.x, d = threadIdx.x;
    float s = 0.0f;
    for (int n = 0; n < 64; n++) s += g_emb[(size_t)(b * 64 + n) * 128 + d];
    out[b * 128 + d] = s * (1.0f / 64.0f);
}

// ============================================================================
// host
// ============================================================================
extern "C" void kernel_launch(void* const* d_in, const int* in_sizes, int n_in,
                              void* d_out, int out_size)
{
    if (n_in < 21) return;
    bool dict = (in_sizes[3] == BB * NNODE * NNODE);

    const float *nf, *st, *ef, *Wn, *bn, *We, *be, *l1g, *l1b,
                *Wq, *Wk, *Wv, *Wo, *bo, *l2g, *l2b, *W1, *b1, *W2, *b2;
    const void* mask;

    if (dict) {
        nf  = (const float*)d_in[0];  st  = (const float*)d_in[1];
        ef  = (const float*)d_in[2];  mask = d_in[3];
        Wn  = (const float*)d_in[4];  bn  = (const float*)d_in[5];
        We  = (const float*)d_in[6];  be  = (const float*)d_in[7];
        l1g = (const float*)d_in[8];  l1b = (const float*)d_in[9];
        Wq  = (const float*)d_in[10]; Wk  = (const float*)d_in[11];
        Wv  = (const float*)d_in[12]; Wo  = (const float*)d_in[13];
        bo  = (const float*)d_in[14]; l2g = (const float*)d_in[15];
        l2b = (const float*)d_in[16]; W1  = (const float*)d_in[17];
        b1  = (const float*)d_in[18]; W2  = (const float*)d_in[19];
        b2  = (const float*)d_in[20];
    } else {
        nf  = (const float*)d_in[0];  st  = (const float*)d_in[1];
        ef  = (const float*)d_in[2];
        Wn  = (const float*)d_in[3];  bn  = (const float*)d_in[4];
        We  = (const float*)d_in[5];  be  = (const float*)d_in[6];
        l1g = (const float*)d_in[7];  l1b = (const float*)d_in[8];
        Wq  = (const float*)d_in[9];  Wk  = (const float*)d_in[10];
        Wv  = (const float*)d_in[11]; Wo  = (const float*)d_in[12];
        bo  = (const float*)d_in[13]; l2g = (const float*)d_in[14];
        l2b = (const float*)d_in[15]; W1  = (const float*)d_in[16];
        b1  = (const float*)d_in[17]; W2  = (const float*)d_in[18];
        b2  = (const float*)d_in[19]; mask = d_in[20];
    }

    float *p_emb, *p_cvec, *p_qkv;
    __nv_bfloat16 *p_x0h, *p_x0l, *p_hh, *p_hl, *p_mhah, *p_mhal, *p_ffh, *p_ffl;
    __nv_bfloat16 *p_WnImg, *p_WprojImg, *p_WbigImg, *p_W1Img, *p_W2Img;
    cudaGetSymbolAddress((void**)&p_emb,   g_emb);
    cudaGetSymbolAddress((void**)&p_cvec,  g_cvec);
    cudaGetSymbolAddress((void**)&p_x0h,   g_x0h);
    cudaGetSymbolAddress((void**)&p_x0l,   g_x0l);
    cudaGetSymbolAddress((void**)&p_hh,    g_hh);
    cudaGetSymbolAddress((void**)&p_hl,    g_hl);
    cudaGetSymbolAddress((void**)&p_mhah,  g_mhah);
    cudaGetSymbolAddress((void**)&p_mhal,  g_mhal);
    cudaGetSymbolAddress((void**)&p_ffh,   g_ffh);
    cudaGetSymbolAddress((void**)&p_ffl,   g_ffl);
    cudaGetSymbolAddress((void**)&p_qkv,   g_qkv);
    cudaGetSymbolAddress((void**)&p_WnImg,   g_WnImg);
    cudaGetSymbolAddress((void**)&p_WprojImg, g_WprojImg);
    cudaGetSymbolAddress((void**)&p_WbigImg,  g_WbigImg);
    cudaGetSymbolAddress((void**)&p_W1Img,    g_W1Img);
    cudaGetSymbolAddress((void**)&p_W2Img,    g_W2Img);

    const int ATTN_SMEM = ATTN_SMEM_FLOATS * 4;
    cudaFuncSetAttribute(attn_kernel, cudaFuncAttributeMaxDynamicSharedMemorySize, ATTN_SMEM);

    float* out = (float*)d_out;
    size_t need_attn = (size_t)BB * DD + (size_t)LLAYERS * NHH * BB * NNODE * NNODE;
    int write_attn = ((size_t)out_size >= need_attn) ? 1 : 0;
    float* attn_base = out + BB * DD;

    fused_prep<<<PREP_BLOCKS, 256>>>(Wn, Wq, Wk, Wv, We, Wo, W1, W2, be, bo);
    detect_mask_kernel<<<1, 256>>>((const unsigned char*)mask);
    concat_kernel<<<(ROWS * 64 + 255) / 256, 256>>>(nf, st);
    // 4th launch: Wn GEMM (ncu capture slot)
    mm_mma<<<dim3(2, 64), 128>>>(p_x0h, p_x0l, p_WnImg, 128, 256,
        bn, nullptr, 0, p_emb, 128, nullptr, nullptr, 0, 0);

    for (int l = 0; l < LLAYERS; l++) {
        const float* be_l = be + (size_t)l * 128;
        ln_kernel<<<512, 256>>>(p_emb, l1g + l * 128, l1b + l * 128, 1e-5f);
        mm_mma<<<dim3(16, 64), 128>>>(p_hh, p_hl,
            p_WprojImg + (size_t)l * 2 * 128 * 1024, 1024, 128,
            nullptr, nullptr, 0, p_qkv, 1024, nullptr, nullptr, 0, 0);

        attn_kernel<<<dim3(32, 64), 256, ATTN_SMEM>>>(ef, mask, be_l,
                                                      attn_base, write_attn, l);

        // emb = mha @ Wbig + cvec + residual   (split-K x4)
        mm_split<<<dim3(2, 64, 4), 128>>>(p_mhah, p_mhal,
            p_WbigImg + (size_t)l * 2 * 512 * 128, 128, 512);
        split_reduce<<<2048, 256>>>(p_cvec + l * 128, p_emb);

        ln_kernel<<<512, 256>>>(p_emb, l2g + l * 128, l2b + l * 128, 1e-6f);
        mm_mma<<<dim3(8, 64), 128>>>(p_hh, p_hl,
            p_W1Img + (size_t)l * 2 * 128 * 512, 512, 128,
            b1 + (size_t)l * 512, nullptr, 0, nullptr, 0, p_ffh, p_ffl, 512, 1);

        // emb = ffn @ W2 + b2 + residual   (split-K x4)
        mm_split<<<dim3(2, 64, 4), 128>>>(p_ffh, p_ffl,
            p_W2Img + (size_t)l * 2 * 512 * 128, 128, 512);
        split_reduce<<<2048, 256>>>(b2 + (size_t)l * 128, p_emb);
    }

    mean_kernel<<<BB, 128>>>(out);
}

// round 15
// speedup vs baseline: 1.0930x; 1.0102x over previous
#include <cuda_runtime.h>
#include <cuda_bf16.h>
#include <math.h>
#include <stdint.h>

// Problem dims
#define BB 64
#define NNODE 64
#define DD 128
#define NHH 2
#define LLAYERS 2
#define ROWS (BB*NNODE)          // 4096

// ============================================================================
// Helpers
// ============================================================================
__device__ __forceinline__ uint32_t smem_u32(const void* p) {
    uint32_t a;
    asm("{ .reg .u64 t; cvta.to.shared.u64 t, %1; cvt.u32.u64 %0, t; }"
        : "=r"(a) : "l"(p));
    return a;
}

__device__ __forceinline__ void ldmA(uint32_t* a, uint32_t addr) {
    asm volatile("ldmatrix.sync.aligned.m8n8.x4.shared.b16 {%0,%1,%2,%3}, [%4];"
        : "=r"(a[0]), "=r"(a[1]), "=r"(a[2]), "=r"(a[3]) : "r"(addr));
}
__device__ __forceinline__ void ldmBt(uint32_t* b, uint32_t addr) {
    asm volatile("ldmatrix.sync.aligned.m8n8.x2.trans.shared.b16 {%0,%1}, [%2];"
        : "=r"(b[0]), "=r"(b[1]) : "r"(addr));
}
__device__ __forceinline__ void mma16816(float* d, const uint32_t* a, const uint32_t* b) {
    asm volatile("mma.sync.aligned.m16n8k16.row.col.f32.bf16.bf16.f32 "
        "{%0,%1,%2,%3}, {%4,%5,%6,%7}, {%8,%9}, {%0,%1,%2,%3};"
        : "+f"(d[0]), "+f"(d[1]), "+f"(d[2]), "+f"(d[3])
        : "r"(a[0]), "r"(a[1]), "r"(a[2]), "r"(a[3]), "r"(b[0]), "r"(b[1]));
}
__device__ __forceinline__ void cp16(uint32_t saddr, const void* gptr) {
    asm volatile("cp.async.cg.shared.global [%0], [%1], 16;"
        :: "r"(saddr), "l"(gptr));
}
#define CP_COMMIT() asm volatile("cp.async.commit_group;" ::: "memory")
template <int N>
__device__ __forceinline__ void cp_wait() {
    asm volatile("cp.async.wait_group %0;" :: "n"(N) : "memory");
}

__device__ __forceinline__ void bf16split(float v, __nv_bfloat16* hi, __nv_bfloat16* lo) {
    __nv_bfloat16 h = __float2bfloat16(v);
    *hi = h;
    *lo = __float2bfloat16(v - __bfloat162float(h));
}

// ============================================================================
// Scratch (device globals; no allocation)
// ============================================================================
__device__ __nv_bfloat16 g_x0h [ROWS*256];
__device__ __nv_bfloat16 g_x0l [ROWS*256];
__device__ float         g_emb [ROWS*128];
__device__ __nv_bfloat16 g_hh  [ROWS*128];
__device__ __nv_bfloat16 g_hl  [ROWS*128];
__device__ float         g_qkv [ROWS*1024];
__device__ __nv_bfloat16 g_mhah[ROWS*512];
__device__ __nv_bfloat16 g_mhal[ROWS*512];
__device__ __nv_bfloat16 g_ffh [ROWS*512];
__device__ __nv_bfloat16 g_ffl [ROWS*512];
__device__ float         g_cvec[LLAYERS*128];
__device__ float         g_part[4*ROWS*128];    // split-K partials (8 MB)
__device__ int           g_mask_mode;

// Weight images, natural [K][N] bf16, hi plane then lo plane
__device__ __nv_bfloat16 g_WnImg  [2*256*128];
__device__ __nv_bfloat16 g_WprojImg[LLAYERS][2*128*1024];
__device__ __nv_bfloat16 g_WbigImg [LLAYERS][2*512*128];
__device__ __nv_bfloat16 g_W1Img   [LLAYERS][2*128*512];
__device__ __nv_bfloat16 g_W2Img   [LLAYERS][2*512*128];

// ============================================================================
// mask dtype detection (parallel)
// ============================================================================
__global__ void detect_mask_kernel(const unsigned char* __restrict__ m)
{
    __shared__ int cnt[2];
    if (threadIdx.x < 2) cnt[threadIdx.x] = 0;
    __syncthreads();
    int u8 = 0, f32 = 0;
    for (int i = threadIdx.x; i < 4096; i += 256) {
        unsigned char v = m[i];
        if (v) {
            int r = i & 3;
            if (r == 1) u8++;
            else if (r == 3) f32++;
        }
    }
    if (u8)  atomicAdd(&cnt[0], u8);
    if (f32) atomicAdd(&cnt[1], f32);
    __syncthreads();
    if (threadIdx.x == 0)
        g_mask_mode = cnt[0] ? 0 : (cnt[1] ? 2 : 1);
}
__device__ __forceinline__ bool mask_at(const void* mp, size_t idx, int mode)
{
    if (mode == 0) return ((const unsigned char*)mp)[idx] != 0;
    if (mode == 1) return ((const int*)mp)[idx] != 0;
    return ((const float*)mp)[idx] != 0.0f;
}

// ============================================================================
// Fused prologue: ALL weight-image prep in one kernel (R12 version)
// ============================================================================
#define PREP_BLOCKS (128 + 768 + 256 + 256 + 256 + 512 + 512 + 1)
__global__ void fused_prep(const float* __restrict__ Wn, const float* __restrict__ Wq,
                           const float* __restrict__ Wk, const float* __restrict__ Wv,
                           const float* __restrict__ We, const float* __restrict__ Wo,
                           const float* __restrict__ W1, const float* __restrict__ W2,
                           const float* __restrict__ be, const float* __restrict__ bo)
{
    int blk = blockIdx.x, tid = threadIdx.x;
    __nv_bfloat16 hi, lo;

    if (blk < 128) {
        int t = blk * 256 + tid;
        bf16split(Wn[t], &hi, &lo);
        g_WnImg[t] = hi; g_WnImg[32768 + t] = lo;
        return;
    }
    blk -= 128;
    if (blk < 768) {
        int idx = blk * 256 + tid;
        int l = idx / 98304, r = idx % 98304;
        int k = r / 768, n = r % 768;
        const float* W = (n < 256) ? Wq : (n < 512 ? Wk : Wv);
        float v = W[(size_t)l * 32768 + (size_t)k * 256 + (n & 255)];
        bf16split(v, &hi, &lo);
        g_WprojImg[l][(size_t)k * 1024 + n]          = hi;
        g_WprojImg[l][131072 + (size_t)k * 1024 + n] = lo;
        return;
    }
    blk -= 768;
    if (blk < 256) {
        int idx = blk * 256 + tid;
        int l = idx >> 15, r = idx & 32767;
        int h = r >> 14, r2 = r & 16383;
        int e = r2 >> 7, d = r2 & 127;
        const float* wq = Wq + (size_t)l * 32768 + (size_t)d * 256 + h * 128;
        const float* we = We + (size_t)l * 16384 + (size_t)e * 128;
        float acc = 0.0f;
        #pragma unroll 8
        for (int c = 0; c < 128; c++) acc += wq[c] * we[c];
        size_t o = (size_t)d * 1024 + 768 + h * 128 + e;
        bf16split(acc, &hi, &lo);
        g_WprojImg[l][o] = hi; g_WprojImg[l][131072 + o] = lo;
        return;
    }
    blk -= 256;
    if (blk < 256) {
        int idx = blk * 256 + tid;
        int l = idx >> 15, t2 = idx & 32767;
        bf16split(Wo[(size_t)l * 32768 + t2], &hi, &lo);
        g_WbigImg[l][t2] = hi; g_WbigImg[l][65536 + t2] = lo;
        return;
    }
    blk -= 256;
    if (blk < 256) {
        int idx = blk * 256 + tid;
        int l = idx >> 15, r = idx & 32767;
        int h = r >> 14, r2 = r & 16383;
        int f = r2 >> 7, n = r2 & 127;
        const float* we = We + (size_t)l * 16384 + (size_t)f * 128;
        const float* wo = Wo + (size_t)l * 32768 + (size_t)(h * 128) * 128 + n;
        float acc = 0.0f;
        #pragma unroll 8
        for (int e = 0; e < 128; e++) acc += we[e] * wo[(size_t)e * 128];
        size_t o = (size_t)(256 + h * 128 + f) * 128 + n;
        bf16split(acc, &hi, &lo);
        g_WbigImg[l][o] = hi; g_WbigImg[l][65536 + o] = lo;
        return;
    }
    blk -= 256;
    if (blk < 512) {
        int idx = blk * 256 + tid;
        int l = idx >> 16, t2 = idx & 65535;
        bf16split(W1[(size_t)l * 65536 + t2], &hi, &lo);
        g_W1Img[l][t2] = hi; g_W1Img[l][65536 + t2] = lo;
        return;
    }
    blk -= 512;
    if (blk < 512) {
        int idx = blk * 256 + tid;
        int l = idx >> 16, t2 = idx & 65535;
        bf16split(W2[(size_t)l * 65536 + t2], &hi, &lo);
        g_W2Img[l][t2] = hi; g_W2Img[l][65536 + t2] = lo;
        return;
    }
    blk -= 512;
    {
        int l = tid >> 7, d = tid & 127;
        float acc = bo[l * 128 + d];
        const float* wo = Wo + (size_t)l * 32768;
        const float* bel = be + l * 128;
        for (int r = 0; r < 256; r++) acc += bel[r & 127] * wo[(size_t)r * 128 + d];
        g_cvec[l * 128 + d] = acc;
    }
}

// ============================================================================
// concat(node_feat, stpe) -> bf16 pairs [4096,256]
// ============================================================================
__global__ void concat_kernel(const float* __restrict__ nf, const float* __restrict__ st)
{
    int t = blockIdx.x * blockDim.x + threadIdx.x;
    if (t < ROWS * 64) {
        int row = t >> 6, c4 = t & 63;
        float4 val = (c4 < 32) ? ((const float4*)nf)[row * 32 + c4]
                               : ((const float4*)st)[row * 32 + (c4 - 32)];
        size_t o = (size_t)row * 256 + c4 * 4;
        float vv[4] = {val.x, val.y, val.z, val.w};
        #pragma unroll
        for (int j = 0; j < 4; j++) {
            __nv_bfloat16 hi, lo; bf16split(vv[j], &hi, &lo);
            g_x0h[o + j] = hi; g_x0l[o + j] = lo;
        }
    }
}

// ============================================================================
// LayerNorm -> bf16 pairs (reads g_emb)
// ============================================================================
__global__ void ln_kernel(const float* __restrict__ x,
                          const float* __restrict__ g, const float* __restrict__ b,
                          float eps)
{
    int row  = blockIdx.x * 8 + (threadIdx.x >> 5);
    int lane = threadIdx.x & 31;
    const float* xr = x + (size_t)row * 128;
    float v0 = xr[lane], v1 = xr[lane + 32], v2 = xr[lane + 64], v3 = xr[lane + 96];
    float s = v0 + v1 + v2 + v3;
    #pragma unroll
    for (int o = 16; o; o >>= 1) s += __shfl_xor_sync(0xffffffffu, s, o);
    float mu = s * (1.0f / 128.0f);
    float d0 = v0 - mu, d1 = v1 - mu, d2 = v2 - mu, d3 = v3 - mu;
    float q = d0*d0 + d1*d1 + d2*d2 + d3*d3;
    #pragma unroll
    for (int o = 16; o; o >>= 1) q += __shfl_xor_sync(0xffffffffu, q, o);
    float inv = rsqrtf(q * (1.0f / 128.0f) + eps);
    size_t base = (size_t)row * 128;
    float y0 = d0 * inv * g[lane]      + b[lane];
    float y1 = d1 * inv * g[lane + 32] + b[lane + 32];
    float y2 = d2 * inv * g[lane + 64] + b[lane + 64];
    float y3 = d3 * inv * g[lane + 96] + b[lane + 96];
    __nv_bfloat16 hi, lo;
    bf16split(y0, &hi, &lo); g_hh[base + lane]      = hi; g_hl[base + lane]      = lo;
    bf16split(y1, &hi, &lo); g_hh[base + lane + 32] = hi; g_hl[base + lane + 32] = lo;
    bf16split(y2, &hi, &lo); g_hh[base + lane + 64] = hi; g_hl[base + lane + 64] = lo;
    bf16split(y3, &hi, &lo); g_hh[base + lane + 96] = hi; g_hl[base + lane + 96] = lo;
}

// ============================================================================
// mma.sync GEMM with cp.async double-buffering (128 thr, 4 warps).
// 64x64 tile, warp tile 32x32, K-chunk 32.
// ============================================================================
#define AKP 40
#define BNP 72
__global__ __launch_bounds__(128) void mm_mma(
    const __nv_bfloat16* __restrict__ Ah, const __nv_bfloat16* __restrict__ Al,
    const __nv_bfloat16* __restrict__ Wimg, int N, int K,
    const float* __restrict__ bias,
    const float* __restrict__ res, int ldr,
    float* __restrict__ outf, int ldo,
    __nv_bfloat16* __restrict__ oh, __nv_bfloat16* __restrict__ ol, int ldp,
    int relu)
{
    __shared__ __nv_bfloat16 sA[2][2][64 * AKP];
    __shared__ __nv_bfloat16 sB[2][2][32 * BNP];

    int tid = threadIdx.x, lane = tid & 31, wid = tid >> 5;
    int m0 = blockIdx.y * 64, n0 = blockIdx.x * 64;
    int wm = (wid >> 1) * 32, wn = (wid & 1) * 32;

    const __nv_bfloat16* Wh = Wimg;
    const __nv_bfloat16* Wl = Wimg + (size_t)N * K;

    float acc[2][4][4];
    #pragma unroll
    for (int mt = 0; mt < 2; mt++)
        #pragma unroll
        for (int nt = 0; nt < 4; nt++)
            #pragma unroll
            for (int c = 0; c < 4; c++) acc[mt][nt][c] = 0.0f;

    uint32_t sA_b[2][2], sB_b[2][2];
    #pragma unroll
    for (int s = 0; s < 2; s++)
        #pragma unroll
        for (int p = 0; p < 2; p++) {
            sA_b[s][p] = smem_u32(sA[s][p]);
            sB_b[s][p] = smem_u32(sB[s][p]);
        }

    int ar0 = tid >> 2, ac0 = (tid & 3) * 8;
    int br0 = tid >> 3, bc0 = (tid & 7) * 8;
    int la_row = lane & 15, la_col = (lane >> 4) * 8;
    int lb_row = lane & 15;

    int nch = K >> 5;

    {
        #pragma unroll
        for (int i = 0; i < 2; i++) {
            int ar = ar0 + i * 32;
            cp16(sA_b[0][0] + (uint32_t)(ar * AKP + ac0) * 2,
                 Ah + (size_t)(m0 + ar) * K + ac0);
            cp16(sA_b[0][1] + (uint32_t)(ar * AKP + ac0) * 2,
                 Al + (size_t)(m0 + ar) * K + ac0);
            int br = br0 + i * 16;
            cp16(sB_b[0][0] + (uint32_t)(br * BNP + bc0) * 2,
                 Wh + (size_t)br * N + n0 + bc0);
            cp16(sB_b[0][1] + (uint32_t)(br * BNP + bc0) * 2,
                 Wl + (size_t)br * N + n0 + bc0);
        }
        CP_COMMIT();
    }

    for (int ch = 0; ch < nch; ch++) {
        int st = ch & 1;
        bool more = (ch + 1 < nch);
        if (more) {
            int k0 = (ch + 1) << 5;
            int s2 = st ^ 1;
            #pragma unroll
            for (int i = 0; i < 2; i++) {
                int ar = ar0 + i * 32;
                cp16(sA_b[s2][0] + (uint32_t)(ar * AKP + ac0) * 2,
                     Ah + (size_t)(m0 + ar) * K + k0 + ac0);
                cp16(sA_b[s2][1] + (uint32_t)(ar * AKP + ac0) * 2,
                     Al + (size_t)(m0 + ar) * K + k0 + ac0);
                int br = br0 + i * 16;
                cp16(sB_b[s2][0] + (uint32_t)(br * BNP + bc0) * 2,
                     Wh + (size_t)(k0 + br) * N + n0 + bc0);
                cp16(sB_b[s2][1] + (uint32_t)(br * BNP + bc0) * 2,
                     Wl + (size_t)(k0 + br) * N + n0 + bc0);
            }
            CP_COMMIT();
            cp_wait<1>();
        } else {
            cp_wait<0>();
        }
        __syncthreads();

        #pragma unroll
        for (int ks = 0; ks < 2; ks++) {
            int kb = ks * 16;
            uint32_t bH[4][2], bL[4][2];
            #pragma unroll
            for (int nt = 0; nt < 4; nt++) {
                uint32_t boff = (uint32_t)((kb + lb_row) * BNP + wn + nt * 8) * 2;
                ldmBt(bH[nt], sB_b[st][0] + boff);
                ldmBt(bL[nt], sB_b[st][1] + boff);
            }
            #pragma unroll
            for (int mt = 0; mt < 2; mt++) {
                uint32_t aoff = (uint32_t)((wm + mt * 16 + la_row) * AKP + kb + la_col) * 2;
                uint32_t aH[4], aL[4];
                ldmA(aH, sA_b[st][0] + aoff);
                ldmA(aL, sA_b[st][1] + aoff);
                #pragma unroll
                for (int nt = 0; nt < 4; nt++) {
                    mma16816(acc[mt][nt], aH, bH[nt]);
                    mma16816(acc[mt][nt], aH, bL[nt]);
                    mma16816(acc[mt][nt], aL, bH[nt]);
                }
            }
        }
        __syncthreads();
    }

    int g = lane >> 2, tg = lane & 3;
    #pragma unroll
    for (int mt = 0; mt < 2; mt++) {
        #pragma unroll
        for (int nt = 0; nt < 4; nt++) {
            int col = n0 + wn + nt * 8 + tg * 2;
            #pragma unroll
            for (int half = 0; half < 2; half++) {
                int row = m0 + wm + mt * 16 + g + half * 8;
                float v0 = acc[mt][nt][half * 2];
                float v1 = acc[mt][nt][half * 2 + 1];
                if (bias) { v0 += bias[col]; v1 += bias[col + 1]; }
                if (res) {
                    v0 += res[(size_t)row * ldr + col];
                    v1 += res[(size_t)row * ldr + col + 1];
                }
                if (relu) { v0 = fmaxf(v0, 0.0f); v1 = fmaxf(v1, 0.0f); }
                if (outf) {
                    outf[(size_t)row * ldo + col]     = v0;
                    outf[(size_t)row * ldo + col + 1] = v1;
                }
                if (oh) {
                    __nv_bfloat16 hi, lo;
                    bf16split(v0, &hi, &lo);
                    oh[(size_t)row * ldp + col] = hi;
                    ol[(size_t)row * ldp + col] = lo;
                    bf16split(v1, &hi, &lo);
                    oh[(size_t)row * ldp + col + 1] = hi;
                    ol[(size_t)row * ldp + col + 1] = lo;
                }
            }
        }
    }
}

// ============================================================================
// Split-K GEMM: K=512 split into 4 slices of 128 via blockIdx.z (R12 version).
// Writes fp32 partials to g_part[z]. N must be 128. Grid (2, 64, 4).
// ============================================================================
__global__ __launch_bounds__(128) void mm_split(
    const __nv_bfloat16* __restrict__ Ah, const __nv_bfloat16* __restrict__ Al,
    const __nv_bfloat16* __restrict__ Wimg, int N, int K)
{
    __shared__ __nv_bfloat16 sA[2][2][64 * AKP];
    __shared__ __nv_bfloat16 sB[2][2][32 * BNP];

    int tid = threadIdx.x, lane = tid & 31, wid = tid >> 5;
    int m0 = blockIdx.y * 64, n0 = blockIdx.x * 64;
    int z = blockIdx.z;
    int kbase = z << 7;                    // 128 per slice
    int wm = (wid >> 1) * 32, wn = (wid & 1) * 32;

    const __nv_bfloat16* Wh = Wimg;
    const __nv_bfloat16* Wl = Wimg + (size_t)N * K;

    float acc[2][4][4];
    #pragma unroll
    for (int mt = 0; mt < 2; mt++)
        #pragma unroll
        for (int nt = 0; nt < 4; nt++)
            #pragma unroll
            for (int c = 0; c < 4; c++) acc[mt][nt][c] = 0.0f;

    uint32_t sA_b[2][2], sB_b[2][2];
    #pragma unroll
    for (int s = 0; s < 2; s++)
        #pragma unroll
        for (int p = 0; p < 2; p++) {
            sA_b[s][p] = smem_u32(sA[s][p]);
            sB_b[s][p] = smem_u32(sB[s][p]);
        }

    int ar0 = tid >> 2, ac0 = (tid & 3) * 8;
    int br0 = tid >> 3, bc0 = (tid & 7) * 8;
    int la_row = lane & 15, la_col = (lane >> 4) * 8;
    int lb_row = lane & 15;

    {
        #pragma unroll
        for (int i = 0; i < 2; i++) {
            int ar = ar0 + i * 32;
            cp16(sA_b[0][0] + (uint32_t)(ar * AKP + ac0) * 2,
                 Ah + (size_t)(m0 + ar) * K + kbase + ac0);
            cp16(sA_b[0][1] + (uint32_t)(ar * AKP + ac0) * 2,
                 Al + (size_t)(m0 + ar) * K + kbase + ac0);
            int br = br0 + i * 16;
            cp16(sB_b[0][0] + (uint32_t)(br * BNP + bc0) * 2,
                 Wh + (size_t)(kbase + br) * N + n0 + bc0);
            cp16(sB_b[0][1] + (uint32_t)(br * BNP + bc0) * 2,
                 Wl + (size_t)(kbase + br) * N + n0 + bc0);
        }
        CP_COMMIT();
    }

    for (int ch = 0; ch < 4; ch++) {
        int st = ch & 1;
        bool more = (ch + 1 < 4);
        if (more) {
            int k0 = kbase + ((ch + 1) << 5);
            int s2 = st ^ 1;
            #pragma unroll
            for (int i = 0; i < 2; i++) {
                int ar = ar0 + i * 32;
                cp16(sA_b[s2][0] + (uint32_t)(ar * AKP + ac0) * 2,
                     Ah + (size_t)(m0 + ar) * K + k0 + ac0);
                cp16(sA_b[s2][1] + (uint32_t)(ar * AKP + ac0) * 2,
                     Al + (size_t)(m0 + ar) * K + k0 + ac0);
                int br = br0 + i * 16;
                cp16(sB_b[s2][0] + (uint32_t)(br * BNP + bc0) * 2,
                     Wh + (size_t)(k0 + br) * N + n0 + bc0);
                cp16(sB_b[s2][1] + (uint32_t)(br * BNP + bc0) * 2,
                     Wl + (size_t)(k0 + br) * N + n0 + bc0);
            }
            CP_COMMIT();
            cp_wait<1>();
        } else {
            cp_wait<0>();
        }
        __syncthreads();

        #pragma unroll
        for (int ks = 0; ks < 2; ks++) {
            int kb = ks * 16;
            uint32_t bH[4][2], bL[4][2];
            #pragma unroll
            for (int nt = 0; nt < 4; nt++) {
                uint32_t boff = (uint32_t)((kb + lb_row) * BNP + wn + nt * 8) * 2;
                ldmBt(bH[nt], sB_b[st][0] + boff);
                ldmBt(bL[nt], sB_b[st][1] + boff);
            }
            #pragma unroll
            for (int mt = 0; mt < 2; mt++) {
                uint32_t aoff = (uint32_t)((wm + mt * 16 + la_row) * AKP + kb + la_col) * 2;
                uint32_t aH[4], aL[4];
                ldmA(aH, sA_b[st][0] + aoff);
                ldmA(aL, sA_b[st][1] + aoff);
                #pragma unroll
                for (int nt = 0; nt < 4; nt++) {
                    mma16816(acc[mt][nt], aH, bH[nt]);
                    mma16816(acc[mt][nt], aH, bL[nt]);
                    mma16816(acc[mt][nt], aL, bH[nt]);
                }
            }
        }
        __syncthreads();
    }

    float* part = g_part + (size_t)z * ROWS * 128;
    int g = lane >> 2, tg = lane & 3;
    #pragma unroll
    for (int mt = 0; mt < 2; mt++) {
        #pragma unroll
        for (int nt = 0; nt < 4; nt++) {
            int col = n0 + wn + nt * 8 + tg * 2;
            #pragma unroll
            for (int half = 0; half < 2; half++) {
                int row = m0 + wm + mt * 16 + g + half * 8;
                part[(size_t)row * 128 + col]     = acc[mt][nt][half * 2];
                part[(size_t)row * 128 + col + 1] = acc[mt][nt][half * 2 + 1];
            }
        }
    }
}

// ============================================================================
// Fused: split-K reduce (4 slices) + bias + residual -> emb, then LN -> hh/hl
// 8 rows/block (1 warp per row), grid 512.
// ============================================================================
__global__ void reduce_ln(const float* __restrict__ bias,
                          const float* __restrict__ g, const float* __restrict__ b,
                          float eps)
{
    int row  = blockIdx.x * 8 + (threadIdx.x >> 5);
    int lane = threadIdx.x & 31;
    size_t base = (size_t)row * 128;

    float y[4];
    #pragma unroll
    for (int m = 0; m < 4; m++) {
        int c = lane + 32 * m;
        float s = g_part[base + c] + g_part[ROWS*128 + base + c]
                + g_part[2*ROWS*128 + base + c] + g_part[3*ROWS*128 + base + c];
        s = s + bias[c] + g_emb[base + c];
        g_emb[base + c] = s;
        y[m] = s;
    }
    float s = y[0] + y[1] + y[2] + y[3];
    #pragma unroll
    for (int o = 16; o; o >>= 1) s += __shfl_xor_sync(0xffffffffu, s, o);
    float mu = s * (1.0f / 128.0f);
    float d0 = y[0] - mu, d1 = y[1] - mu, d2 = y[2] - mu, d3 = y[3] - mu;
    float q = d0*d0 + d1*d1 + d2*d2 + d3*d3;
    #pragma unroll
    for (int o = 16; o; o >>= 1) q += __shfl_xor_sync(0xffffffffu, q, o);
    float inv = rsqrtf(q * (1.0f / 128.0f) + eps);
    __nv_bfloat16 hi, lo;
    bf16split(d0 * inv * g[lane]      + b[lane],      &hi, &lo);
    g_hh[base + lane]      = hi; g_hl[base + lane]      = lo;
    bf16split(d1 * inv * g[lane + 32] + b[lane + 32], &hi, &lo);
    g_hh[base + lane + 32] = hi; g_hl[base + lane + 32] = lo;
    bf16split(d2 * inv * g[lane + 64] + b[lane + 64], &hi, &lo);
    g_hh[base + lane + 64] = hi; g_hl[base + lane + 64] = lo;
    bf16split(d3 * inv * g[lane + 96] + b[lane + 96], &hi, &lo);
    g_hh[base + lane + 96] = hi; g_hl[base + lane + 96] = lo;
}

// plain reduce (final W2 of layer 1; no LN after)
__global__ void split_reduce(const float* __restrict__ bias,
                             float* __restrict__ inout)
{
    int o = blockIdx.x * 256 + threadIdx.x;
    float s = g_part[o] + g_part[o + ROWS*128] + g_part[o + 2*ROWS*128]
            + g_part[o + 3*ROWS*128];
    inout[o] = s + bias[o & 127] + inout[o];
}

// ============================================================================
// fused attention v3 — 2 query rows per CTA, partial-sum buffer (unchanged)
// ============================================================================
#define ATTN_SMEM_FLOATS (16384 + 8192 + 512 + 512 + 256 + 256 + 128)
__global__ __launch_bounds__(256) void attn_kernel(
    const float* __restrict__ edge,
    const void* __restrict__ mask,
    const float* __restrict__ be_l,
    float* __restrict__ attn_out, int write_attn,
    int layer)
{
    extern __shared__ float sm[];
    float* s_e    = sm;
    float* s_part = s_e + 16384;
    float* s_q    = s_part + 8192;
    float* s_qe   = s_q + 512;
    float* s_sc   = s_qe + 512;
    float* s_att  = s_sc + 256;
    float* s_be   = s_att + 256;

    int b = blockIdx.y, i0 = blockIdx.x * 2;
    int t = threadIdx.x, lane = t & 31, w = t >> 5;
    int mode = g_mask_mode;
    size_t qrow0 = (size_t)(b * 64 + i0) * 1024;

    const float4* esrc = (const float4*)(edge + ((size_t)(b * 64 + i0)) * 8192);
    #pragma unroll
    for (int r = 0; r < 16; r++)
        ((float4*)s_e)[t + r * 256] = esrc[t + r * 256];
    s_q [t]       = g_qkv[qrow0 + t];
    s_q [256 + t] = g_qkv[qrow0 + 1024 + t];
    s_qe[t]       = g_qkv[qrow0 + 768 + t];
    s_qe[256 + t] = g_qkv[qrow0 + 1024 + 768 + t];
    if (t < 128) s_be[t] = be_l[t];
    __syncthreads();

    {
        int h = w >> 2;
        float4 q0  = *(float4*)&s_q [h * 128 + lane * 4];
        float4 q1  = *(float4*)&s_q [256 + h * 128 + lane * 4];
        float4 qe0 = *(float4*)&s_qe[h * 128 + lane * 4];
        float4 qe1 = *(float4*)&s_qe[256 + h * 128 + lane * 4];
        float4 be4 = *(float4*)&s_be[lane * 4];
        float qb0 = q0.x*be4.x + q0.y*be4.y + q0.z*be4.z + q0.w*be4.w;
        float qb1 = q1.x*be4.x + q1.y*be4.y + q1.z*be4.z + q1.w*be4.w;
        #pragma unroll
        for (int off = 16; off; off >>= 1) {
            qb0 += __shfl_xor_sync(0xffffffffu, qb0, off);
            qb1 += __shfl_xor_sync(0xffffffffu, qb1, off);
        }

        #pragma unroll
        for (int oo = 0; oo < 16; oo++) {
            int j = (w & 3) * 16 + oo;
            float4 k4 = *(const float4*)(g_qkv + (size_t)(b * 64 + j) * 1024
                                         + 256 + h * 128 + lane * 4);
            float4 e0 = *(float4*)&s_e[j * 128 + lane * 4];
            float4 e1 = *(float4*)&s_e[8192 + j * 128 + lane * 4];
            float d0 = q0.x*k4.x + q0.y*k4.y + q0.z*k4.z + q0.w*k4.w
                     + qe0.x*e0.x + qe0.y*e0.y + qe0.z*e0.z + qe0.w*e0.w;
            float d1 = q1.x*k4.x + q1.y*k4.y + q1.z*k4.z + q1.w*k4.w
                     + qe1.x*e1.x + qe1.y*e1.y + qe1.z*e1.z + qe1.w*e1.w;
            #pragma unroll
            for (int off = 16; off; off >>= 1) {
                d0 += __shfl_xor_sync(0xffffffffu, d0, off);
                d1 += __shfl_xor_sync(0xffffffffu, d1, off);
            }
            if (lane == 0) {
                s_sc[h * 64 + j]       = d0 + qb0;
                s_sc[128 + h * 64 + j] = d1 + qb1;
            }
        }
    }
    __syncthreads();

    if (w < 4) {
        const float invT = 0.08838834764831843f;
        int ii = w >> 1, h = w & 1;
        int iabs = i0 + ii;
        size_t mbase = ((size_t)(b * 64 + iabs)) * 64;
        float v0 = s_sc[ii * 128 + h * 64 + lane]      * invT;
        float v1 = s_sc[ii * 128 + h * 64 + lane + 32] * invT;
        if (mask_at(mask, mbase + lane,      mode)) v0 = 1e-10f;
        if (mask_at(mask, mbase + lane + 32, mode)) v1 = 1e-10f;
        float mx = fmaxf(v0, v1);
        #pragma unroll
        for (int off = 16; off; off >>= 1)
            mx = fmaxf(mx, __shfl_xor_sync(0xffffffffu, mx, off));
        float e0 = expf(v0 - mx), e1 = expf(v1 - mx);
        float s = e0 + e1;
        #pragma unroll
        for (int off = 16; off; off >>= 1)
            s += __shfl_xor_sync(0xffffffffu, s, off);
        float inv = 1.0f / s;
        e0 *= inv; e1 *= inv;
        s_att[ii * 128 + h * 64 + lane]      = e0;
        s_att[ii * 128 + h * 64 + lane + 32] = e1;
        if (write_attn) {
            float* ap = attn_out +
                ((((size_t)layer * NHH + h) * BB + b) * NNODE + iabs) * NNODE;
            ap[lane]      = e0;
            ap[lane + 32] = e1;
        }
    }
    __syncthreads();

    {
        float a0h0[4] = {}, a0h1[4] = {}, a0e0[4] = {}, a0e1[4] = {};
        float a1h0[4] = {}, a1h1[4] = {}, a1e0[4] = {}, a1e1[4] = {};
        #pragma unroll
        for (int jj = 0; jj < 8; jj++) {
            int j = w + jj * 8;
            const float* vrow = g_qkv + (size_t)(b * 64 + j) * 1024 + 512;
            float4 v0 = *(const float4*)(vrow + lane * 4);
            float4 v1 = *(const float4*)(vrow + 128 + lane * 4);
            float4 e0 = *(float4*)&s_e[j * 128 + lane * 4];
            float4 e1 = *(float4*)&s_e[8192 + j * 128 + lane * 4];
            float w00 = s_att[j],       w01 = s_att[64 + j];
            float w10 = s_att[128 + j], w11 = s_att[192 + j];
            a0h0[0] += w00*v0.x; a0h0[1] += w00*v0.y; a0h0[2] += w00*v0.z; a0h0[3] += w00*v0.w;
            a0h1[0] += w01*v1.x; a0h1[1] += w01*v1.y; a0h1[2] += w01*v1.z; a0h1[3] += w01*v1.w;
            a0e0[0] += w00*e0.x; a0e0[1] += w00*e0.y; a0e0[2] += w00*e0.z; a0e0[3] += w00*e0.w;
            a0e1[0] += w01*e0.x; a0e1[1] += w01*e0.y; a0e1[2] += w01*e0.z; a0e1[3] += w01*e0.w;
            a1h0[0] += w10*v0.x; a1h0[1] += w10*v0.y; a1h0[2] += w10*v0.z; a1h0[3] += w10*v0.w;
            a1h1[0] += w11*v1.x; a1h1[1] += w11*v1.y; a1h1[2] += w11*v1.z; a1h1[3] += w11*v1.w;
            a1e0[0] += w10*e1.x; a1e0[1] += w10*e1.y; a1e0[2] += w10*e1.z; a1e0[3] += w10*e1.w;
            a1e1[0] += w11*e1.x; a1e1[1] += w11*e1.y; a1e1[2] += w11*e1.z; a1e1[3] += w11*e1.w;
        }
        float* pw = s_part + w * 1024;
        *(float4*)&pw[lane * 4]       = make_float4(a0h0[0], a0h0[1], a0h0[2], a0h0[3]);
        *(float4*)&pw[128 + lane * 4] = make_float4(a0h1[0], a0h1[1], a0h1[2], a0h1[3]);
        *(float4*)&pw[256 + lane * 4] = make_float4(a0e0[0], a0e0[1], a0e0[2], a0e0[3]);
        *(float4*)&pw[384 + lane * 4] = make_float4(a0e1[0], a0e1[1], a0e1[2], a0e1[3]);
        *(float4*)&pw[512 + lane * 4] = make_float4(a1h0[0], a1h0[1], a1h0[2], a1h0[3]);
        *(float4*)&pw[640 + lane * 4] = make_float4(a1h1[0], a1h1[1], a1h1[2], a1h1[3]);
        *(float4*)&pw[768 + lane * 4] = make_float4(a1e0[0], a1e0[1], a1e0[2], a1e0[3]);
        *(float4*)&pw[896 + lane * 4] = make_float4(a1e1[0], a1e1[1], a1e1[2], a1e1[3]);
    }
    __syncthreads();

    #pragma unroll
    for (int rep = 0; rep < 4; rep++) {
        int o = t + rep * 256;
        float s = 0.0f;
        #pragma unroll
        for (int ww = 0; ww < 8; ww++) s += s_part[ww * 1024 + o];
        int ii = o >> 9, seg = o & 511;
        size_t mo = ((size_t)(b * 64 + i0 + ii)) * 512 + seg;
        __nv_bfloat16 hi, lo; bf16split(s, &hi, &lo);
        g_mhah[mo] = hi; g_mhal[mo] = lo;
    }
}

// ---------------- final mean over nodes ----------------
__global__ void mean_kernel(float* __restrict__ out)
{
    int b = blockIdx.x, d = threadIdx.x;
    float s = 0.0f;
    for (int n = 0; n < 64; n++) s += g_emb[(size_t)(b * 64 + n) * 128 + d];
    out[b * 128 + d] = s * (1.0f / 64.0f);
}

// ============================================================================
// host
// ============================================================================
extern "C" void kernel_launch(void* const* d_in, const int* in_sizes, int n_in,
                              void* d_out, int out_size)
{
    if (n_in < 21) return;
    bool dict = (in_sizes[3] == BB * NNODE * NNODE);

    const float *nf, *st, *ef, *Wn, *bn, *We, *be, *l1g, *l1b,
                *Wq, *Wk, *Wv, *Wo, *bo, *l2g, *l2b, *W1, *b1, *W2, *b2;
    const void* mask;

    if (dict) {
        nf  = (const float*)d_in[0];  st  = (const float*)d_in[1];
        ef  = (const float*)d_in[2];  mask = d_in[3];
        Wn  = (const float*)d_in[4];  bn  = (const float*)d_in[5];
        We  = (const float*)d_in[6];  be  = (const float*)d_in[7];
        l1g = (const float*)d_in[8];  l1b = (const float*)d_in[9];
        Wq  = (const float*)d_in[10]; Wk  = (const float*)d_in[11];
        Wv  = (const float*)d_in[12]; Wo  = (const float*)d_in[13];
        bo  = (const float*)d_in[14]; l2g = (const float*)d_in[15];
        l2b = (const float*)d_in[16]; W1  = (const float*)d_in[17];
        b1  = (const float*)d_in[18]; W2  = (const float*)d_in[19];
        b2  = (const float*)d_in[20];
    } else {
        nf  = (const float*)d_in[0];  st  = (const float*)d_in[1];
        ef  = (const float*)d_in[2];
        Wn  = (const float*)d_in[3];  bn  = (const float*)d_in[4];
        We  = (const float*)d_in[5];  be  = (const float*)d_in[6];
        l1g = (const float*)d_in[7];  l1b = (const float*)d_in[8];
        Wq  = (const float*)d_in[9];  Wk  = (const float*)d_in[10];
        Wv  = (const float*)d_in[11]; Wo  = (const float*)d_in[12];
        bo  = (const float*)d_in[13]; l2g = (const float*)d_in[14];
        l2b = (const float*)d_in[15]; W1  = (const float*)d_in[16];
        b1  = (const float*)d_in[17]; W2  = (const float*)d_in[18];
        b2  = (const float*)d_in[19]; mask = d_in[20];
    }

    float *p_emb, *p_cvec, *p_qkv;
    __nv_bfloat16 *p_x0h, *p_x0l, *p_hh, *p_hl, *p_mhah, *p_mhal, *p_ffh, *p_ffl;
    __nv_bfloat16 *p_WnImg, *p_WprojImg, *p_WbigImg, *p_W1Img, *p_W2Img;
    cudaGetSymbolAddress((void**)&p_emb,   g_emb);
    cudaGetSymbolAddress((void**)&p_cvec,  g_cvec);
    cudaGetSymbolAddress((void**)&p_x0h,   g_x0h);
    cudaGetSymbolAddress((void**)&p_x0l,   g_x0l);
    cudaGetSymbolAddress((void**)&p_hh,    g_hh);
    cudaGetSymbolAddress((void**)&p_hl,    g_hl);
    cudaGetSymbolAddress((void**)&p_mhah,  g_mhah);
    cudaGetSymbolAddress((void**)&p_mhal,  g_mhal);
    cudaGetSymbolAddress((void**)&p_ffh,   g_ffh);
    cudaGetSymbolAddress((void**)&p_ffl,   g_ffl);
    cudaGetSymbolAddress((void**)&p_qkv,   g_qkv);
    cudaGetSymbolAddress((void**)&p_WnImg,   g_WnImg);
    cudaGetSymbolAddress((void**)&p_WprojImg, g_WprojImg);
    cudaGetSymbolAddress((void**)&p_WbigImg,  g_WbigImg);
    cudaGetSymbolAddress((void**)&p_W1Img,    g_W1Img);
    cudaGetSymbolAddress((void**)&p_W2Img,    g_W2Img);

    const int ATTN_SMEM = ATTN_SMEM_FLOATS * 4;
    cudaFuncSetAttribute(attn_kernel, cudaFuncAttributeMaxDynamicSharedMemorySize, ATTN_SMEM);

    float* out = (float*)d_out;
    size_t need_attn = (size_t)BB * DD + (size_t)LLAYERS * NHH * BB * NNODE * NNODE;
    int write_attn = ((size_t)out_size >= need_attn) ? 1 : 0;
    float* attn_base = out + BB * DD;

    fused_prep<<<PREP_BLOCKS, 256>>>(Wn, Wq, Wk, Wv, We, Wo, W1, W2, be, bo);
    detect_mask_kernel<<<1, 256>>>((const unsigned char*)mask);
    concat_kernel<<<(ROWS * 64 + 255) / 256, 256>>>(nf, st);
    // 4th launch: Wn GEMM (ncu capture slot, unchanged from R12)
    mm_mma<<<dim3(2, 64), 128>>>(p_x0h, p_x0l, p_WnImg, 128, 256,
        bn, nullptr, 0, p_emb, 128, nullptr, nullptr, 0, 0);
    // ln1 of layer 0
    ln_kernel<<<512, 256>>>(p_emb, l1g, l1b, 1e-5f);

    for (int l = 0; l < LLAYERS; l++) {
        const float* be_l = be + (size_t)l * 128;
        // fused q|k|v|qe projection
        mm_mma<<<dim3(16, 64), 128>>>(p_hh, p_hl,
            p_WprojImg + (size_t)l * 2 * 128 * 1024, 1024, 128,
            nullptr, nullptr, 0, p_qkv, 1024, nullptr, nullptr, 0, 0);

        attn_kernel<<<dim3(32, 64), 256, ATTN_SMEM>>>(ef, mask, be_l,
                                                      attn_base, write_attn, l);

        // emb = mha @ Wbig + cvec + residual, fused with ln2 -> hh/hl
        mm_split<<<dim3(2, 64, 4), 128>>>(p_mhah, p_mhal,
            p_WbigImg + (size_t)l * 2 * 512 * 128, 128, 512);
        reduce_ln<<<512, 256>>>(p_cvec + l * 128,
                                l2g + l * 128, l2b + l * 128, 1e-6f);

        // FFN up (relu) -> ffh/ffl
        mm_mma<<<dim3(8, 64), 128>>>(p_hh, p_hl,
            p_W1Img + (size_t)l * 2 * 128 * 512, 512, 128,
            b1 + (size_t)l * 512, nullptr, 0, nullptr, 0, p_ffh, p_ffl, 512, 1);

        // FFN down split-K
        mm_split<<<dim3(2, 64, 4), 128>>>(p_ffh, p_ffl,
            p_W2Img + (size_t)l * 2 * 512 * 128, 128, 512);
        if (l + 1 < LLAYERS) {
            // fused: reduce + b2 + residual, then ln1 of NEXT layer
            reduce_ln<<<512, 256>>>(b2 + (size_t)l * 128,
                                    l1g + (l + 1) * 128, l1b + (l + 1) * 128,
                                    1e-5f);
        } else {
            split_reduce<<<2048, 256>>>(b2 + (size_t)l * 128, p_emb);
        }
    }

    mean_kernel<<<BB, 128>>>(out);
}

// round 16
// speedup vs baseline: 1.0941x; 1.0010x over previous
#include <cuda_runtime.h>
#include <cuda_bf16.h>
#include <math.h>
#include <stdint.h>

// Problem dims
#define BB 64
#define NNODE 64
#define DD 128
#define NHH 2
#define LLAYERS 2
#define ROWS (BB*NNODE)          // 4096

// ============================================================================
// Helpers
// ============================================================================
__device__ __forceinline__ uint32_t smem_u32(const void* p) {
    uint32_t a;
    asm("{ .reg .u64 t; cvta.to.shared.u64 t, %1; cvt.u32.u64 %0, t; }"
        : "=r"(a) : "l"(p));
    return a;
}

__device__ __forceinline__ void ldmA(uint32_t* a, uint32_t addr) {
    asm volatile("ldmatrix.sync.aligned.m8n8.x4.shared.b16 {%0,%1,%2,%3}, [%4];"
        : "=r"(a[0]), "=r"(a[1]), "=r"(a[2]), "=r"(a[3]) : "r"(addr));
}
__device__ __forceinline__ void ldmBt(uint32_t* b, uint32_t addr) {
    asm volatile("ldmatrix.sync.aligned.m8n8.x2.trans.shared.b16 {%0,%1}, [%2];"
        : "=r"(b[0]), "=r"(b[1]) : "r"(addr));
}
__device__ __forceinline__ void mma16816(float* d, const uint32_t* a, const uint32_t* b) {
    asm volatile("mma.sync.aligned.m16n8k16.row.col.f32.bf16.bf16.f32 "
        "{%0,%1,%2,%3}, {%4,%5,%6,%7}, {%8,%9}, {%0,%1,%2,%3};"
        : "+f"(d[0]), "+f"(d[1]), "+f"(d[2]), "+f"(d[3])
        : "r"(a[0]), "r"(a[1]), "r"(a[2]), "r"(a[3]), "r"(b[0]), "r"(b[1]));
}
__device__ __forceinline__ void cp16(uint32_t saddr, const void* gptr) {
    asm volatile("cp.async.cg.shared.global [%0], [%1], 16;"
        :: "r"(saddr), "l"(gptr));
}
#define CP_COMMIT() asm volatile("cp.async.commit_group;" ::: "memory")
template <int N>
__device__ __forceinline__ void cp_wait() {
    asm volatile("cp.async.wait_group %0;" :: "n"(N) : "memory");
}

__device__ __forceinline__ void bf16split(float v, __nv_bfloat16* hi, __nv_bfloat16* lo) {
    __nv_bfloat16 h = __float2bfloat16(v);
    *hi = h;
    *lo = __float2bfloat16(v - __bfloat162float(h));
}

// ============================================================================
// Scratch (device globals; no allocation)
// ============================================================================
__device__ __nv_bfloat16 g_x0h [ROWS*256];
__device__ __nv_bfloat16 g_x0l [ROWS*256];
__device__ float         g_emb [ROWS*128];
__device__ __nv_bfloat16 g_hh  [ROWS*128];
__device__ __nv_bfloat16 g_hl  [ROWS*128];
__device__ float         g_qkv [ROWS*1024];
__device__ __nv_bfloat16 g_mhah[ROWS*512];
__device__ __nv_bfloat16 g_mhal[ROWS*512];
__device__ __nv_bfloat16 g_ffh [ROWS*512];
__device__ __nv_bfloat16 g_ffl [ROWS*512];
__device__ float         g_cvec[LLAYERS*128];
__device__ float         g_part[4*ROWS*128];    // split-K partials (8 MB)
__device__ int           g_mask_mode;

// Weight images, natural [K][N] bf16, hi plane then lo plane
__device__ __nv_bfloat16 g_WnImg  [2*256*128];
__device__ __nv_bfloat16 g_WprojImg[LLAYERS][2*128*1024];
__device__ __nv_bfloat16 g_WbigImg [LLAYERS][2*512*128];
__device__ __nv_bfloat16 g_W1Img   [LLAYERS][2*128*512];
__device__ __nv_bfloat16 g_W2Img   [LLAYERS][2*512*128];

__device__ __forceinline__ bool mask_at(const void* mp, size_t idx, int mode)
{
    if (mode == 0) return ((const unsigned char*)mp)[idx] != 0;
    if (mode == 1) return ((const int*)mp)[idx] != 0;
    return ((const float*)mp)[idx] != 0.0f;
}

// ============================================================================
// Fused prologue: weight prep + concat + mask detect, one kernel.
// Blocks: wn 128 | wqkv 768 | wqe 256 | wo 256 | wbigc 256 | w1 512 | w2 512 |
//         cvec 1 | concat 1024 | detect 1
// ============================================================================
#define PREP_BLOCKS (128 + 768 + 256 + 256 + 256 + 512 + 512 + 1 + 1024 + 1)
__global__ void fused_prep(const float* __restrict__ Wn, const float* __restrict__ Wq,
                           const float* __restrict__ Wk, const float* __restrict__ Wv,
                           const float* __restrict__ We, const float* __restrict__ Wo,
                           const float* __restrict__ W1, const float* __restrict__ W2,
                           const float* __restrict__ be, const float* __restrict__ bo,
                           const float* __restrict__ nf, const float* __restrict__ st,
                           const unsigned char* __restrict__ mask)
{
    int blk = blockIdx.x, tid = threadIdx.x;
    __nv_bfloat16 hi, lo;

    if (blk < 128) {
        int t = blk * 256 + tid;
        bf16split(Wn[t], &hi, &lo);
        g_WnImg[t] = hi; g_WnImg[32768 + t] = lo;
        return;
    }
    blk -= 128;
    if (blk < 768) {
        int idx = blk * 256 + tid;
        int l = idx / 98304, r = idx % 98304;
        int k = r / 768, n = r % 768;
        const float* W = (n < 256) ? Wq : (n < 512 ? Wk : Wv);
        float v = W[(size_t)l * 32768 + (size_t)k * 256 + (n & 255)];
        bf16split(v, &hi, &lo);
        g_WprojImg[l][(size_t)k * 1024 + n]          = hi;
        g_WprojImg[l][131072 + (size_t)k * 1024 + n] = lo;
        return;
    }
    blk -= 768;
    if (blk < 256) {
        int idx = blk * 256 + tid;
        int l = idx >> 15, r = idx & 32767;
        int h = r >> 14, r2 = r & 16383;
        int e = r2 >> 7, d = r2 & 127;
        const float* wq = Wq + (size_t)l * 32768 + (size_t)d * 256 + h * 128;
        const float* we = We + (size_t)l * 16384 + (size_t)e * 128;
        float acc = 0.0f;
        #pragma unroll 8
        for (int c = 0; c < 128; c++) acc += wq[c] * we[c];
        size_t o = (size_t)d * 1024 + 768 + h * 128 + e;
        bf16split(acc, &hi, &lo);
        g_WprojImg[l][o] = hi; g_WprojImg[l][131072 + o] = lo;
        return;
    }
    blk -= 256;
    if (blk < 256) {
        int idx = blk * 256 + tid;
        int l = idx >> 15, t2 = idx & 32767;
        bf16split(Wo[(size_t)l * 32768 + t2], &hi, &lo);
        g_WbigImg[l][t2] = hi; g_WbigImg[l][65536 + t2] = lo;
        return;
    }
    blk -= 256;
    if (blk < 256) {
        int idx = blk * 256 + tid;
        int l = idx >> 15, r = idx & 32767;
        int h = r >> 14, r2 = r & 16383;
        int f = r2 >> 7, n = r2 & 127;
        const float* we = We + (size_t)l * 16384 + (size_t)f * 128;
        const float* wo = Wo + (size_t)l * 32768 + (size_t)(h * 128) * 128 + n;
        float acc = 0.0f;
        #pragma unroll 8
        for (int e = 0; e < 128; e++) acc += we[e] * wo[(size_t)e * 128];
        size_t o = (size_t)(256 + h * 128 + f) * 128 + n;
        bf16split(acc, &hi, &lo);
        g_WbigImg[l][o] = hi; g_WbigImg[l][65536 + o] = lo;
        return;
    }
    blk -= 256;
    if (blk < 512) {
        int idx = blk * 256 + tid;
        int l = idx >> 16, t2 = idx & 65535;
        bf16split(W1[(size_t)l * 65536 + t2], &hi, &lo);
        g_W1Img[l][t2] = hi; g_W1Img[l][65536 + t2] = lo;
        return;
    }
    blk -= 512;
    if (blk < 512) {
        int idx = blk * 256 + tid;
        int l = idx >> 16, t2 = idx & 65535;
        bf16split(W2[(size_t)l * 65536 + t2], &hi, &lo);
        g_W2Img[l][t2] = hi; g_W2Img[l][65536 + t2] = lo;
        return;
    }
    blk -= 512;
    if (blk < 1) {
        int l = tid >> 7, d = tid & 127;
        float acc = bo[l * 128 + d];
        const float* wo = Wo + (size_t)l * 32768;
        const float* bel = be + l * 128;
        for (int r = 0; r < 256; r++) acc += bel[r & 127] * wo[(size_t)r * 128 + d];
        g_cvec[l * 128 + d] = acc;
        return;
    }
    blk -= 1;
    if (blk < 1024) {                        // concat
        int t = blk * 256 + tid;             // over 262144 float4
        int row = t >> 6, c4 = t & 63;
        float4 val = (c4 < 32) ? ((const float4*)nf)[row * 32 + c4]
                               : ((const float4*)st)[row * 32 + (c4 - 32)];
        size_t o = (size_t)row * 256 + c4 * 4;
        float vv[4] = {val.x, val.y, val.z, val.w};
        #pragma unroll
        for (int j = 0; j < 4; j++) {
            bf16split(vv[j], &hi, &lo);
            g_x0h[o + j] = hi; g_x0l[o + j] = lo;
        }
        return;
    }
    // detect mask dtype (1 block)
    {
        __shared__ int cnt[2];
        if (tid < 2) cnt[tid] = 0;
        __syncthreads();
        int u8 = 0, f32 = 0;
        for (int i = tid; i < 4096; i += 256) {
            unsigned char v = mask[i];
            if (v) {
                int r = i & 3;
                if (r == 1) u8++;
                else if (r == 3) f32++;
            }
        }
        if (u8)  atomicAdd(&cnt[0], u8);
        if (f32) atomicAdd(&cnt[1], f32);
        __syncthreads();
        if (tid == 0)
            g_mask_mode = cnt[0] ? 0 : (cnt[1] ? 2 : 1);
    }
}

// ============================================================================
// mma.sync GEMM with cp.async double-buffering (128 thr, 4 warps).
// 64x64 tile, warp tile 32x32, K-chunk 32.
// ============================================================================
#define AKP 40
#define BNP 72
__global__ __launch_bounds__(128) void mm_mma(
    const __nv_bfloat16* __restrict__ Ah, const __nv_bfloat16* __restrict__ Al,
    const __nv_bfloat16* __restrict__ Wimg, int N, int K,
    const float* __restrict__ bias,
    const float* __restrict__ res, int ldr,
    float* __restrict__ outf, int ldo,
    __nv_bfloat16* __restrict__ oh, __nv_bfloat16* __restrict__ ol, int ldp,
    int relu)
{
    __shared__ __nv_bfloat16 sA[2][2][64 * AKP];
    __shared__ __nv_bfloat16 sB[2][2][32 * BNP];

    int tid = threadIdx.x, lane = tid & 31, wid = tid >> 5;
    int m0 = blockIdx.y * 64, n0 = blockIdx.x * 64;
    int wm = (wid >> 1) * 32, wn = (wid & 1) * 32;

    const __nv_bfloat16* Wh = Wimg;
    const __nv_bfloat16* Wl = Wimg + (size_t)N * K;

    float acc[2][4][4];
    #pragma unroll
    for (int mt = 0; mt < 2; mt++)
        #pragma unroll
        for (int nt = 0; nt < 4; nt++)
            #pragma unroll
            for (int c = 0; c < 4; c++) acc[mt][nt][c] = 0.0f;

    uint32_t sA_b[2][2], sB_b[2][2];
    #pragma unroll
    for (int s = 0; s < 2; s++)
        #pragma unroll
        for (int p = 0; p < 2; p++) {
            sA_b[s][p] = smem_u32(sA[s][p]);
            sB_b[s][p] = smem_u32(sB[s][p]);
        }

    int ar0 = tid >> 2, ac0 = (tid & 3) * 8;
    int br0 = tid >> 3, bc0 = (tid & 7) * 8;
    int la_row = lane & 15, la_col = (lane >> 4) * 8;
    int lb_row = lane & 15;

    int nch = K >> 5;

    {
        #pragma unroll
        for (int i = 0; i < 2; i++) {
            int ar = ar0 + i * 32;
            cp16(sA_b[0][0] + (uint32_t)(ar * AKP + ac0) * 2,
                 Ah + (size_t)(m0 + ar) * K + ac0);
            cp16(sA_b[0][1] + (uint32_t)(ar * AKP + ac0) * 2,
                 Al + (size_t)(m0 + ar) * K + ac0);
            int br = br0 + i * 16;
            cp16(sB_b[0][0] + (uint32_t)(br * BNP + bc0) * 2,
                 Wh + (size_t)br * N + n0 + bc0);
            cp16(sB_b[0][1] + (uint32_t)(br * BNP + bc0) * 2,
                 Wl + (size_t)br * N + n0 + bc0);
        }
        CP_COMMIT();
    }

    for (int ch = 0; ch < nch; ch++) {
        int st = ch & 1;
        bool more = (ch + 1 < nch);
        if (more) {
            int k0 = (ch + 1) << 5;
            int s2 = st ^ 1;
            #pragma unroll
            for (int i = 0; i < 2; i++) {
                int ar = ar0 + i * 32;
                cp16(sA_b[s2][0] + (uint32_t)(ar * AKP + ac0) * 2,
                     Ah + (size_t)(m0 + ar) * K + k0 + ac0);
                cp16(sA_b[s2][1] + (uint32_t)(ar * AKP + ac0) * 2,
                     Al + (size_t)(m0 + ar) * K + k0 + ac0);
                int br = br0 + i * 16;
                cp16(sB_b[s2][0] + (uint32_t)(br * BNP + bc0) * 2,
                     Wh + (size_t)(k0 + br) * N + n0 + bc0);
                cp16(sB_b[s2][1] + (uint32_t)(br * BNP + bc0) * 2,
                     Wl + (size_t)(k0 + br) * N + n0 + bc0);
            }
            CP_COMMIT();
            cp_wait<1>();
        } else {
            cp_wait<0>();
        }
        __syncthreads();

        #pragma unroll
        for (int ks = 0; ks < 2; ks++) {
            int kb = ks * 16;
            uint32_t bH[4][2], bL[4][2];
            #pragma unroll
            for (int nt = 0; nt < 4; nt++) {
                uint32_t boff = (uint32_t)((kb + lb_row) * BNP + wn + nt * 8) * 2;
                ldmBt(bH[nt], sB_b[st][0] + boff);
                ldmBt(bL[nt], sB_b[st][1] + boff);
            }
            #pragma unroll
            for (int mt = 0; mt < 2; mt++) {
                uint32_t aoff = (uint32_t)((wm + mt * 16 + la_row) * AKP + kb + la_col) * 2;
                uint32_t aH[4], aL[4];
                ldmA(aH, sA_b[st][0] + aoff);
                ldmA(aL, sA_b[st][1] + aoff);
                #pragma unroll
                for (int nt = 0; nt < 4; nt++) {
                    mma16816(acc[mt][nt], aH, bH[nt]);
                    mma16816(acc[mt][nt], aH, bL[nt]);
                    mma16816(acc[mt][nt], aL, bH[nt]);
                }
            }
        }
        __syncthreads();
    }

    int g = lane >> 2, tg = lane & 3;
    #pragma unroll
    for (int mt = 0; mt < 2; mt++) {
        #pragma unroll
        for (int nt = 0; nt < 4; nt++) {
            int col = n0 + wn + nt * 8 + tg * 2;
            #pragma unroll
            for (int half = 0; half < 2; half++) {
                int row = m0 + wm + mt * 16 + g + half * 8;
                float v0 = acc[mt][nt][half * 2];
                float v1 = acc[mt][nt][half * 2 + 1];
                if (bias) { v0 += bias[col]; v1 += bias[col + 1]; }
                if (res) {
                    v0 += res[(size_t)row * ldr + col];
                    v1 += res[(size_t)row * ldr + col + 1];
                }
                if (relu) { v0 = fmaxf(v0, 0.0f); v1 = fmaxf(v1, 0.0f); }
                if (outf) {
                    outf[(size_t)row * ldo + col]     = v0;
                    outf[(size_t)row * ldo + col + 1] = v1;
                }
                if (oh) {
                    __nv_bfloat16 hi, lo;
                    bf16split(v0, &hi, &lo);
                    oh[(size_t)row * ldp + col] = hi;
                    ol[(size_t)row * ldp + col] = lo;
                    bf16split(v1, &hi, &lo);
                    oh[(size_t)row * ldp + col + 1] = hi;
                    ol[(size_t)row * ldp + col + 1] = lo;
                }
            }
        }
    }
}

// ============================================================================
// Split-K GEMM: K split into gridDim.z slices via blockIdx.z.
// Writes fp32 partials to g_part[z]. N must be 128.
// ============================================================================
__global__ __launch_bounds__(128) void mm_split(
    const __nv_bfloat16* __restrict__ Ah, const __nv_bfloat16* __restrict__ Al,
    const __nv_bfloat16* __restrict__ Wimg, int N, int K)
{
    __shared__ __nv_bfloat16 sA[2][2][64 * AKP];
    __shared__ __nv_bfloat16 sB[2][2][32 * BNP];

    int tid = threadIdx.x, lane = tid & 31, wid = tid >> 5;
    int m0 = blockIdx.y * 64, n0 = blockIdx.x * 64;
    int z = blockIdx.z;
    int kslice = K / gridDim.z;
    int nch = kslice >> 5;
    int kbase = z * kslice;
    int wm = (wid >> 1) * 32, wn = (wid & 1) * 32;

    const __nv_bfloat16* Wh = Wimg;
    const __nv_bfloat16* Wl = Wimg + (size_t)N * K;

    float acc[2][4][4];
    #pragma unroll
    for (int mt = 0; mt < 2; mt++)
        #pragma unroll
        for (int nt = 0; nt < 4; nt++)
            #pragma unroll
            for (int c = 0; c < 4; c++) acc[mt][nt][c] = 0.0f;

    uint32_t sA_b[2][2], sB_b[2][2];
    #pragma unroll
    for (int s = 0; s < 2; s++)
        #pragma unroll
        for (int p = 0; p < 2; p++) {
            sA_b[s][p] = smem_u32(sA[s][p]);
            sB_b[s][p] = smem_u32(sB[s][p]);
        }

    int ar0 = tid >> 2, ac0 = (tid & 3) * 8;
    int br0 = tid >> 3, bc0 = (tid & 7) * 8;
    int la_row = lane & 15, la_col = (lane >> 4) * 8;
    int lb_row = lane & 15;

    {
        #pragma unroll
        for (int i = 0; i < 2; i++) {
            int ar = ar0 + i * 32;
            cp16(sA_b[0][0] + (uint32_t)(ar * AKP + ac0) * 2,
                 Ah + (size_t)(m0 + ar) * K + kbase + ac0);
            cp16(sA_b[0][1] + (uint32_t)(ar * AKP + ac0) * 2,
                 Al + (size_t)(m0 + ar) * K + kbase + ac0);
            int br = br0 + i * 16;
            cp16(sB_b[0][0] + (uint32_t)(br * BNP + bc0) * 2,
                 Wh + (size_t)(kbase + br) * N + n0 + bc0);
            cp16(sB_b[0][1] + (uint32_t)(br * BNP + bc0) * 2,
                 Wl + (size_t)(kbase + br) * N + n0 + bc0);
        }
        CP_COMMIT();
    }

    for (int ch = 0; ch < nch; ch++) {
        int st = ch & 1;
        bool more = (ch + 1 < nch);
        if (more) {
            int k0 = kbase + ((ch + 1) << 5);
            int s2 = st ^ 1;
            #pragma unroll
            for (int i = 0; i < 2; i++) {
                int ar = ar0 + i * 32;
                cp16(sA_b[s2][0] + (uint32_t)(ar * AKP + ac0) * 2,
                     Ah + (size_t)(m0 + ar) * K + k0 + ac0);
                cp16(sA_b[s2][1] + (uint32_t)(ar * AKP + ac0) * 2,
                     Al + (size_t)(m0 + ar) * K + k0 + ac0);
                int br = br0 + i * 16;
                cp16(sB_b[s2][0] + (uint32_t)(br * BNP + bc0) * 2,
                     Wh + (size_t)(k0 + br) * N + n0 + bc0);
                cp16(sB_b[s2][1] + (uint32_t)(br * BNP + bc0) * 2,
                     Wl + (size_t)(k0 + br) * N + n0 + bc0);
            }
            CP_COMMIT();
            cp_wait<1>();
        } else {
            cp_wait<0>();
        }
        __syncthreads();

        #pragma unroll
        for (int ks = 0; ks < 2; ks++) {
            int kb = ks * 16;
            uint32_t bH[4][2], bL[4][2];
            #pragma unroll
            for (int nt = 0; nt < 4; nt++) {
                uint32_t boff = (uint32_t)((kb + lb_row) * BNP + wn + nt * 8) * 2;
                ldmBt(bH[nt], sB_b[st][0] + boff);
                ldmBt(bL[nt], sB_b[st][1] + boff);
            }
            #pragma unroll
            for (int mt = 0; mt < 2; mt++) {
                uint32_t aoff = (uint32_t)((wm + mt * 16 + la_row) * AKP + kb + la_col) * 2;
                uint32_t aH[4], aL[4];
                ldmA(aH, sA_b[st][0] + aoff);
                ldmA(aL, sA_b[st][1] + aoff);
                #pragma unroll
                for (int nt = 0; nt < 4; nt++) {
                    mma16816(acc[mt][nt], aH, bH[nt]);
                    mma16816(acc[mt][nt], aH, bL[nt]);
                    mma16816(acc[mt][nt], aL, bH[nt]);
                }
            }
        }
        __syncthreads();
    }

    float* part = g_part + (size_t)z * ROWS * 128;
    int g = lane >> 2, tg = lane & 3;
    #pragma unroll
    for (int mt = 0; mt < 2; mt++) {
        #pragma unroll
        for (int nt = 0; nt < 4; nt++) {
            int col = n0 + wn + nt * 8 + tg * 2;
            #pragma unroll
            for (int half = 0; half < 2; half++) {
                int row = m0 + wm + mt * 16 + g + half * 8;
                part[(size_t)row * 128 + col]     = acc[mt][nt][half * 2];
                part[(size_t)row * 128 + col + 1] = acc[mt][nt][half * 2 + 1];
            }
        }
    }
}

// ============================================================================
// Fused: split-K reduce + bias (+residual) -> emb, then LayerNorm -> hh/hl.
// 8 rows/block (1 warp per row), grid 512.
// ============================================================================
__global__ void reduce_ln(const float* __restrict__ bias,
                          const float* __restrict__ g, const float* __restrict__ b,
                          float eps, int nsl, int use_res)
{
    int row  = blockIdx.x * 8 + (threadIdx.x >> 5);
    int lane = threadIdx.x & 31;
    size_t base = (size_t)row * 128;

    float y[4];
    #pragma unroll
    for (int m = 0; m < 4; m++) {
        int c = lane + 32 * m;
        float s = g_part[base + c];
        for (int z = 1; z < nsl; z++) s += g_part[(size_t)z * ROWS * 128 + base + c];
        s += bias[c];
        if (use_res) s += g_emb[base + c];
        g_emb[base + c] = s;
        y[m] = s;
    }
    float s = y[0] + y[1] + y[2] + y[3];
    #pragma unroll
    for (int o = 16; o; o >>= 1) s += __shfl_xor_sync(0xffffffffu, s, o);
    float mu = s * (1.0f / 128.0f);
    float d0 = y[0] - mu, d1 = y[1] - mu, d2 = y[2] - mu, d3 = y[3] - mu;
    float q = d0*d0 + d1*d1 + d2*d2 + d3*d3;
    #pragma unroll
    for (int o = 16; o; o >>= 1) q += __shfl_xor_sync(0xffffffffu, q, o);
    float inv = rsqrtf(q * (1.0f / 128.0f) + eps);
    __nv_bfloat16 hi, lo;
    bf16split(d0 * inv * g[lane]      + b[lane],      &hi, &lo);
    g_hh[base + lane]      = hi; g_hl[base + lane]      = lo;
    bf16split(d1 * inv * g[lane + 32] + b[lane + 32], &hi, &lo);
    g_hh[base + lane + 32] = hi; g_hl[base + lane + 32] = lo;
    bf16split(d2 * inv * g[lane + 64] + b[lane + 64], &hi, &lo);
    g_hh[base + lane + 64] = hi; g_hl[base + lane + 64] = lo;
    bf16split(d3 * inv * g[lane + 96] + b[lane + 96], &hi, &lo);
    g_hh[base + lane + 96] = hi; g_hl[base + lane + 96] = lo;
}

// plain reduce (final W2 of layer 1; no LN needed after)
__global__ void split_reduce(const float* __restrict__ bias,
                             float* __restrict__ inout)
{
    int o = blockIdx.x * 256 + threadIdx.x;
    float s = g_part[o] + g_part[o + ROWS*128] + g_part[o + 2*ROWS*128]
            + g_part[o + 3*ROWS*128];
    inout[o] = s + bias[o & 127] + inout[o];
}

// ============================================================================
// fused attention v3 — 2 query rows per CTA, partial-sum buffer (unchanged)
// ============================================================================
#define ATTN_SMEM_FLOATS (16384 + 8192 + 512 + 512 + 256 + 256 + 128)
__global__ __launch_bounds__(256) void attn_kernel(
    const float* __restrict__ edge,
    const void* __restrict__ mask,
    const float* __restrict__ be_l,
    float* __restrict__ attn_out, int write_attn,
    int layer)
{
    extern __shared__ float sm[];
    float* s_e    = sm;
    float* s_part = s_e + 16384;
    float* s_q    = s_part + 8192;
    float* s_qe   = s_q + 512;
    float* s_sc   = s_qe + 512;
    float* s_att  = s_sc + 256;
    float* s_be   = s_att + 256;

    int b = blockIdx.y, i0 = blockIdx.x * 2;
    int t = threadIdx.x, lane = t & 31, w = t >> 5;
    int mode = g_mask_mode;
    size_t qrow0 = (size_t)(b * 64 + i0) * 1024;

    const float4* esrc = (const float4*)(edge + ((size_t)(b * 64 + i0)) * 8192);
    #pragma unroll
    for (int r = 0; r < 16; r++)
        ((float4*)s_e)[t + r * 256] = esrc[t + r * 256];
    s_q [t]       = g_qkv[qrow0 + t];
    s_q [256 + t] = g_qkv[qrow0 + 1024 + t];
    s_qe[t]       = g_qkv[qrow0 + 768 + t];
    s_qe[256 + t] = g_qkv[qrow0 + 1024 + 768 + t];
    if (t < 128) s_be[t] = be_l[t];
    __syncthreads();

    {
        int h = w >> 2;
        float4 q0  = *(float4*)&s_q [h * 128 + lane * 4];
        float4 q1  = *(float4*)&s_q [256 + h * 128 + lane * 4];
        float4 qe0 = *(float4*)&s_qe[h * 128 + lane * 4];
        float4 qe1 = *(float4*)&s_qe[256 + h * 128 + lane * 4];
        float4 be4 = *(float4*)&s_be[lane * 4];
        float qb0 = q0.x*be4.x + q0.y*be4.y + q0.z*be4.z + q0.w*be4.w;
        float qb1 = q1.x*be4.x + q1.y*be4.y + q1.z*be4.z + q1.w*be4.w;
        #pragma unroll
        for (int off = 16; off; off >>= 1) {
            qb0 += __shfl_xor_sync(0xffffffffu, qb0, off);
            qb1 += __shfl_xor_sync(0xffffffffu, qb1, off);
        }

        #pragma unroll
        for (int oo = 0; oo < 16; oo++) {
            int j = (w & 3) * 16 + oo;
            float4 k4 = *(const float4*)(g_qkv + (size_t)(b * 64 + j) * 1024
                                         + 256 + h * 128 + lane * 4);
            float4 e0 = *(float4*)&s_e[j * 128 + lane * 4];
            float4 e1 = *(float4*)&s_e[8192 + j * 128 + lane * 4];
            float d0 = q0.x*k4.x + q0.y*k4.y + q0.z*k4.z + q0.w*k4.w
                     + qe0.x*e0.x + qe0.y*e0.y + qe0.z*e0.z + qe0.w*e0.w;
            float d1 = q1.x*k4.x + q1.y*k4.y + q1.z*k4.z + q1.w*k4.w
                     + qe1.x*e1.x + qe1.y*e1.y + qe1.z*e1.z + qe1.w*e1.w;
            #pragma unroll
            for (int off = 16; off; off >>= 1) {
                d0 += __shfl_xor_sync(0xffffffffu, d0, off);
                d1 += __shfl_xor_sync(0xffffffffu, d1, off);
            }
            if (lane == 0) {
                s_sc[h * 64 + j]       = d0 + qb0;
                s_sc[128 + h * 64 + j] = d1 + qb1;
            }
        }
    }
    __syncthreads();

    if (w < 4) {
        const float invT = 0.08838834764831843f;
        int ii = w >> 1, h = w & 1;
        int iabs = i0 + ii;
        size_t mbase = ((size_t)(b * 64 + iabs)) * 64;
        float v0 = s_sc[ii * 128 + h * 64 + lane]      * invT;
        float v1 = s_sc[ii * 128 + h * 64 + lane + 32] * invT;
        if (mask_at(mask, mbase + lane,      mode)) v0 = 1e-10f;
        if (mask_at(mask, mbase + lane + 32, mode)) v1 = 1e-10f;
        float mx = fmaxf(v0, v1);
        #pragma unroll
        for (int off = 16; off; off >>= 1)
            mx = fmaxf(mx, __shfl_xor_sync(0xffffffffu, mx, off));
        float e0 = expf(v0 - mx), e1 = expf(v1 - mx);
        float s = e0 + e1;
        #pragma unroll
        for (int off = 16; off; off >>= 1)
            s += __shfl_xor_sync(0xffffffffu, s, off);
        float inv = 1.0f / s;
        e0 *= inv; e1 *= inv;
        s_att[ii * 128 + h * 64 + lane]      = e0;
        s_att[ii * 128 + h * 64 + lane + 32] = e1;
        if (write_attn) {
            float* ap = attn_out +
                ((((size_t)layer * NHH + h) * BB + b) * NNODE + iabs) * NNODE;
            ap[lane]      = e0;
            ap[lane + 32] = e1;
        }
    }
    __syncthreads();

    {
        float a0h0[4] = {}, a0h1[4] = {}, a0e0[4] = {}, a0e1[4] = {};
        float a1h0[4] = {}, a1h1[4] = {}, a1e0[4] = {}, a1e1[4] = {};
        #pragma unroll
        for (int jj = 0; jj < 8; jj++) {
            int j = w + jj * 8;
            const float* vrow = g_qkv + (size_t)(b * 64 + j) * 1024 + 512;
            float4 v0 = *(const float4*)(vrow + lane * 4);
            float4 v1 = *(const float4*)(vrow + 128 + lane * 4);
            float4 e0 = *(float4*)&s_e[j * 128 + lane * 4];
            float4 e1 = *(float4*)&s_e[8192 + j * 128 + lane * 4];
            float w00 = s_att[j],       w01 = s_att[64 + j];
            float w10 = s_att[128 + j], w11 = s_att[192 + j];
            a0h0[0] += w00*v0.x; a0h0[1] += w00*v0.y; a0h0[2] += w00*v0.z; a0h0[3] += w00*v0.w;
            a0h1[0] += w01*v1.x; a0h1[1] += w01*v1.y; a0h1[2] += w01*v1.z; a0h1[3] += w01*v1.w;
            a0e0[0] += w00*e0.x; a0e0[1] += w00*e0.y; a0e0[2] += w00*e0.z; a0e0[3] += w00*e0.w;
            a0e1[0] += w01*e0.x; a0e1[1] += w01*e0.y; a0e1[2] += w01*e0.z; a0e1[3] += w01*e0.w;
            a1h0[0] += w10*v0.x; a1h0[1] += w10*v0.y; a1h0[2] += w10*v0.z; a1h0[3] += w10*v0.w;
            a1h1[0] += w11*v1.x; a1h1[1] += w11*v1.y; a1h1[2] += w11*v1.z; a1h1[3] += w11*v1.w;
            a1e0[0] += w10*e1.x; a1e0[1] += w10*e1.y; a1e0[2] += w10*e1.z; a1e0[3] += w10*e1.w;
            a1e1[0] += w11*e1.x; a1e1[1] += w11*e1.y; a1e1[2] += w11*e1.z; a1e1[3] += w11*e1.w;
        }
        float* pw = s_part + w * 1024;
        *(float4*)&pw[lane * 4]       = make_float4(a0h0[0], a0h0[1], a0h0[2], a0h0[3]);
        *(float4*)&pw[128 + lane * 4] = make_float4(a0h1[0], a0h1[1], a0h1[2], a0h1[3]);
        *(float4*)&pw[256 + lane * 4] = make_float4(a0e0[0], a0e0[1], a0e0[2], a0e0[3]);
        *(float4*)&pw[384 + lane * 4] = make_float4(a0e1[0], a0e1[1], a0e1[2], a0e1[3]);
        *(float4*)&pw[512 + lane * 4] = make_float4(a1h0[0], a1h0[1], a1h0[2], a1h0[3]);
        *(float4*)&pw[640 + lane * 4] = make_float4(a1h1[0], a1h1[1], a1h1[2], a1h1[3]);
        *(float4*)&pw[768 + lane * 4] = make_float4(a1e0[0], a1e0[1], a1e0[2], a1e0[3]);
        *(float4*)&pw[896 + lane * 4] = make_float4(a1e1[0], a1e1[1], a1e1[2], a1e1[3]);
    }
    __syncthreads();

    #pragma unroll
    for (int rep = 0; rep < 4; rep++) {
        int o = t + rep * 256;
        float s = 0.0f;
        #pragma unroll
        for (int ww = 0; ww < 8; ww++) s += s_part[ww * 1024 + o];
        int ii = o >> 9, seg = o & 511;
        size_t mo = ((size_t)(b * 64 + i0 + ii)) * 512 + seg;
        __nv_bfloat16 hi, lo; bf16split(s, &hi, &lo);
        g_mhah[mo] = hi; g_mhal[mo] = lo;
    }
}

// ---------------- final mean over nodes ----------------
__global__ void mean_kernel(float* __restrict__ out)
{
    int b = blockIdx.x, d = threadIdx.x;
    float s = 0.0f;
    for (int n = 0; n < 64; n++) s += g_emb[(size_t)(b * 64 + n) * 128 + d];
    out[b * 128 + d] = s * (1.0f / 64.0f);
}

// ============================================================================
// host
// ============================================================================
extern "C" void kernel_launch(void* const* d_in, const int* in_sizes, int n_in,
                              void* d_out, int out_size)
{
    if (n_in < 21) return;
    bool dict = (in_sizes[3] == BB * NNODE * NNODE);

    const float *nf, *st, *ef, *Wn, *bn, *We, *be, *l1g, *l1b,
                *Wq, *Wk, *Wv, *Wo, *bo, *l2g, *l2b, *W1, *b1, *W2, *b2;
    const void* mask;

    if (dict) {
        nf  = (const float*)d_in[0];  st  = (const float*)d_in[1];
        ef  = (const float*)d_in[2];  mask = d_in[3];
        Wn  = (const float*)d_in[4];  bn  = (const float*)d_in[5];
        We  = (const float*)d_in[6];  be  = (const float*)d_in[7];
        l1g = (const float*)d_in[8];  l1b = (const float*)d_in[9];
        Wq  = (const float*)d_in[10]; Wk  = (const float*)d_in[11];
        Wv  = (const float*)d_in[12]; Wo  = (const float*)d_in[13];
        bo  = (const float*)d_in[14]; l2g = (const float*)d_in[15];
        l2b = (const float*)d_in[16]; W1  = (const float*)d_in[17];
        b1  = (const float*)d_in[18]; W2  = (const float*)d_in[19];
        b2  = (const float*)d_in[20];
    } else {
        nf  = (const float*)d_in[0];  st  = (const float*)d_in[1];
        ef  = (const float*)d_in[2];
        Wn  = (const float*)d_in[3];  bn  = (const float*)d_in[4];
        We  = (const float*)d_in[5];  be  = (const float*)d_in[6];
        l1g = (const float*)d_in[7];  l1b = (const float*)d_in[8];
        Wq  = (const float*)d_in[9];  Wk  = (const float*)d_in[10];
        Wv  = (const float*)d_in[11]; Wo  = (const float*)d_in[12];
        bo  = (const float*)d_in[13]; l2g = (const float*)d_in[14];
        l2b = (const float*)d_in[15]; W1  = (const float*)d_in[16];
        b1  = (const float*)d_in[17]; W2  = (const float*)d_in[18];
        b2  = (const float*)d_in[19]; mask = d_in[20];
    }

    float *p_emb, *p_cvec, *p_qkv;
    __nv_bfloat16 *p_x0h, *p_x0l, *p_hh, *p_hl, *p_mhah, *p_mhal, *p_ffh, *p_ffl;
    __nv_bfloat16 *p_WnImg, *p_WprojImg, *p_WbigImg, *p_W1Img, *p_W2Img;
    cudaGetSymbolAddress((void**)&p_emb,   g_emb);
    cudaGetSymbolAddress((void**)&p_cvec,  g_cvec);
    cudaGetSymbolAddress((void**)&p_x0h,   g_x0h);
    cudaGetSymbolAddress((void**)&p_x0l,   g_x0l);
    cudaGetSymbolAddress((void**)&p_hh,    g_hh);
    cudaGetSymbolAddress((void**)&p_hl,    g_hl);
    cudaGetSymbolAddress((void**)&p_mhah,  g_mhah);
    cudaGetSymbolAddress((void**)&p_mhal,  g_mhal);
    cudaGetSymbolAddress((void**)&p_ffh,   g_ffh);
    cudaGetSymbolAddress((void**)&p_ffl,   g_ffl);
    cudaGetSymbolAddress((void**)&p_qkv,   g_qkv);
    cudaGetSymbolAddress((void**)&p_WnImg,   g_WnImg);
    cudaGetSymbolAddress((void**)&p_WprojImg, g_WprojImg);
    cudaGetSymbolAddress((void**)&p_WbigImg,  g_WbigImg);
    cudaGetSymbolAddress((void**)&p_W1Img,    g_W1Img);
    cudaGetSymbolAddress((void**)&p_W2Img,    g_W2Img);

    const int ATTN_SMEM = ATTN_SMEM_FLOATS * 4;
    cudaFuncSetAttribute(attn_kernel, cudaFuncAttributeMaxDynamicSharedMemorySize, ATTN_SMEM);

    float* out = (float*)d_out;
    size_t need_attn = (size_t)BB * DD + (size_t)LLAYERS * NHH * BB * NNODE * NNODE;
    int write_attn = ((size_t)out_size >= need_attn) ? 1 : 0;
    float* attn_base = out + BB * DD;

    // 1: everything input-independent + concat + mask detect
    fused_prep<<<PREP_BLOCKS, 256>>>(Wn, Wq, Wk, Wv, We, Wo, W1, W2, be, bo,
                                     nf, st, (const unsigned char*)mask);
    // 2: Wn GEMM split-K (K=256, 2 slices)
    mm_split<<<dim3(2, 64, 2), 128>>>(p_x0h, p_x0l, p_WnImg, 128, 256);
    // 3: reduce + bias + ln1(layer 0) -> emb, hh/hl
    reduce_ln<<<512, 256>>>(bn, l1g, l1b, 1e-5f, 2, 0);

    for (int l = 0; l < LLAYERS; l++) {
        const float* be_l = be + (size_t)l * 128;
        // 4 (ncu slot on l==0): fused q|k|v|qe projection
        mm_mma<<<dim3(16, 64), 128>>>(p_hh, p_hl,
            p_WprojImg + (size_t)l * 2 * 128 * 1024, 1024, 128,
            nullptr, nullptr, 0, p_qkv, 1024, nullptr, nullptr, 0, 0);

        attn_kernel<<<dim3(32, 64), 256, ATTN_SMEM>>>(ef, mask, be_l,
                                                      attn_base, write_attn, l);

        // emb = mha @ Wbig + cvec + residual; then ln2 -> hh/hl
        mm_split<<<dim3(2, 64, 4), 128>>>(p_mhah, p_mhal,
            p_WbigImg + (size_t)l * 2 * 512 * 128, 128, 512);
        reduce_ln<<<512, 256>>>(p_cvec + l * 128,
                                l2g + l * 128, l2b + l * 128, 1e-6f, 4, 1);

        // FFN up (relu) -> ffh/ffl
        mm_mma<<<dim3(8, 64), 128>>>(p_hh, p_hl,
            p_W1Img + (size_t)l * 2 * 128 * 512, 512, 128,
            b1 + (size_t)l * 512, nullptr, 0, nullptr, 0, p_ffh, p_ffl, 512, 1);

        // FFN down split-K
        mm_split<<<dim3(2, 64, 4), 128>>>(p_ffh, p_ffl,
            p_W2Img + (size_t)l * 2 * 512 * 128, 128, 512);
        if (l + 1 < LLAYERS) {
            // reduce + b2 + residual, then ln1 of NEXT layer
            reduce_ln<<<512, 256>>>(b2 + (size_t)l * 128,
                                    l1g + (l + 1) * 128, l1b + (l + 1) * 128,
                                    1e-5f, 4, 1);
        } else {
            split_reduce<<<2048, 256>>>(b2 + (size_t)l * 128, p_emb);
        }
    }

    mean_kernel<<<BB, 128>>>(out);
}